// round 3
// baseline (speedup 1.0000x reference)
#include <cuda_runtime.h>

// Problem constants (fixed shapes from reference)
#define B_  8
#define C_  256
#define CK_ 64
#define N_  2304
#define M1_ 384   // combined projection rows: q(64) + k(64) + (gamma@value)(256)

// ---------------- scratch (__device__ globals; no allocation in kernel_launch) ----
__device__ float g_W[M1_ * C_];           // combined projection weight
__device__ float g_bias[M1_];             // combined projection bias
__device__ float g_Y[B_ * M1_ * N_];      // q | k | gv  projections  (28 MB)
__device__ float g_E[B_ * N_ * N_];       // exp(Q^T K)               (170 MB)
__device__ float g_D[B_ * N_];            // row sums of E over keys j
__device__ float g_Vp[B_ * C_ * N_];      // (G V)[c,i] / D[i]        (19 MB)

// ---------------- K0: build combined weights --------------------------------------
// rows [0,64)   = qw, bias qb
// rows [64,128) = kw, bias kb
// rows [128,384): W[128+o][c] = sum_c' gw[o][c'] * vw[c'][c]; bias = gw[o]·vb
__global__ __launch_bounds__(256) void build_w_kernel(
    const float* __restrict__ qw, const float* __restrict__ qb,
    const float* __restrict__ kw, const float* __restrict__ kb,
    const float* __restrict__ vw, const float* __restrict__ vb,
    const float* __restrict__ gw)
{
    __shared__ float sg[256];
    int r = blockIdx.x;
    int t = threadIdx.x;
    if (r < 64) {
        g_W[r * C_ + t] = qw[r * C_ + t];
        if (t == 0) g_bias[r] = qb[r];
    } else if (r < 128) {
        g_W[r * C_ + t] = kw[(r - 64) * C_ + t];
        if (t == 0) g_bias[r] = kb[r - 64];
    } else {
        int o = r - 128;
        sg[t] = gw[o * C_ + t];
        __syncthreads();
        float acc = 0.f;
        #pragma unroll 8
        for (int c2 = 0; c2 < C_; c2++)
            acc = fmaf(sg[c2], vw[c2 * C_ + t], acc);
        g_W[r * C_ + t] = acc;
        if (t == 0) {
            float bb = 0.f;
            for (int c2 = 0; c2 < C_; c2++) bb += sg[c2] * vb[c2];
            g_bias[r] = bb;
        }
    }
}

// ---------------- generic tiled SGEMM: C = A(MxK) * B(KxN) + bias[m] --------------
// 128x128 block tile, BK=16, 256 threads, 8x8 register tile per thread.
// All dims assumed divisible (M%128==0, N%128==0, K%16==0) — true for all uses here.
__global__ __launch_bounds__(256) void sgemm128_kernel(
    const float* __restrict__ A, const float* __restrict__ Bm,
    float* __restrict__ C, const float* __restrict__ bias,
    int M, int N, int K, long sA, long sB, long sC)
{
    const int b = blockIdx.z;
    const float* Ab = A  + (long)b * sA;
    const float* Bb = Bm + (long)b * sB;
    float*       Cb = C  + (long)b * sC;
    const int bm = blockIdx.y * 128;
    const int bn = blockIdx.x * 128;

    __shared__ float As[16][132];   // transposed A tile (k, m), padded
    __shared__ float Bs[16][128];   // (k, n)

    const int tid = threadIdx.x;
    const int tx = tid & 15;        // n direction
    const int ty = tid >> 4;        // m direction

    float acc[8][8];
    #pragma unroll
    for (int i = 0; i < 8; i++)
        #pragma unroll
        for (int j = 0; j < 8; j++) acc[i][j] = 0.f;

    for (int kt = 0; kt < K; kt += 16) {
        // load A tile 128x16 (float4 along K, scatter-transpose into As)
        #pragma unroll
        for (int u = 0; u < 2; u++) {
            int f   = tid + u * 256;      // 0..511
            int row = f >> 2;             // 0..127
            int kk  = (f & 3) * 4;        // 0,4,8,12
            float4 a = *(const float4*)&Ab[(long)(bm + row) * K + kt + kk];
            As[kk + 0][row] = a.x;
            As[kk + 1][row] = a.y;
            As[kk + 2][row] = a.z;
            As[kk + 3][row] = a.w;
        }
        // load B tile 16x128 (float4 along N, direct)
        #pragma unroll
        for (int u = 0; u < 2; u++) {
            int f    = tid + u * 256;
            int krow = f >> 5;            // 0..15
            int col  = (f & 31) * 4;      // 0..124
            *(float4*)&Bs[krow][col] =
                *(const float4*)&Bb[(long)(kt + krow) * N + bn + col];
        }
        __syncthreads();

        #pragma unroll
        for (int k = 0; k < 16; k++) {
            float a[8], bb[8];
            *(float4*)&a[0]  = *(const float4*)&As[k][ty * 8];
            *(float4*)&a[4]  = *(const float4*)&As[k][ty * 8 + 4];
            *(float4*)&bb[0] = *(const float4*)&Bs[k][tx * 8];
            *(float4*)&bb[4] = *(const float4*)&Bs[k][tx * 8 + 4];
            #pragma unroll
            for (int i = 0; i < 8; i++)
                #pragma unroll
                for (int j = 0; j < 8; j++)
                    acc[i][j] = fmaf(a[i], bb[j], acc[i][j]);
        }
        __syncthreads();
    }

    #pragma unroll
    for (int i = 0; i < 8; i++) {
        int row = bm + ty * 8 + i;
        float bv = bias[row];
        #pragma unroll
        for (int j = 0; j < 8; j += 4) {
            float4 v;
            v.x = acc[i][j + 0] + bv;
            v.y = acc[i][j + 1] + bv;
            v.z = acc[i][j + 2] + bv;
            v.w = acc[i][j + 3] + bv;
            *(float4*)&Cb[(long)row * N + bn + tx * 8 + j] = v;
        }
    }
}

// ---------------- zero D ----------------------------------------------------------
__global__ void zero_d_kernel() {
    int i = blockIdx.x * 256 + threadIdx.x;
    if (i < B_ * N_) g_D[i] = 0.f;
}

// ---------------- K2: E[b,i,j] = exp(q_i . k_j), D[b,i] = sum_j E ------------------
// 64x64 output tile, K-dim = 64 fully resident in smem. block (16,16) -> 4x4 micro.
__global__ __launch_bounds__(256) void energy_kernel()
{
    const int b  = blockIdx.z;
    const int i0 = blockIdx.y * 64;
    const int j0 = blockIdx.x * 64;
    const float* q  = g_Y + (long)b * M1_ * N_;          // rows [0,64)
    const float* kk = q + (long)CK_ * N_;                // rows [64,128)

    __shared__ float qs[64][68];
    __shared__ float ks[64][68];

    const int tid = threadIdx.x;
    const int tx = tid & 15;
    const int ty = tid >> 4;

    #pragma unroll
    for (int u = 0; u < 4; u++) {
        int f   = tid + u * 256;          // 0..1023
        int c   = f >> 4;                 // 0..63
        int col = (f & 15) * 4;           // 0..60
        *(float4*)&qs[c][col] = *(const float4*)&q [(long)c * N_ + i0 + col];
        *(float4*)&ks[c][col] = *(const float4*)&kk[(long)c * N_ + j0 + col];
    }
    __syncthreads();

    float acc[4][4];
    #pragma unroll
    for (int i = 0; i < 4; i++)
        #pragma unroll
        for (int j = 0; j < 4; j++) acc[i][j] = 0.f;

    #pragma unroll
    for (int c = 0; c < 64; c++) {
        float4 qv = *(const float4*)&qs[c][ty * 4];
        float4 kv = *(const float4*)&ks[c][tx * 4];
        float qa[4] = {qv.x, qv.y, qv.z, qv.w};
        float ka[4] = {kv.x, kv.y, kv.z, kv.w};
        #pragma unroll
        for (int i = 0; i < 4; i++)
            #pragma unroll
            for (int j = 0; j < 4; j++)
                acc[i][j] = fmaf(qa[i], ka[j], acc[i][j]);
    }

    float* Eb = g_E + (long)b * N_ * N_;
    #pragma unroll
    for (int ii = 0; ii < 4; ii++) {
        float4 e;
        e.x = __expf(acc[ii][0]);
        e.y = __expf(acc[ii][1]);
        e.z = __expf(acc[ii][2]);
        e.w = __expf(acc[ii][3]);
        int ig = i0 + ty * 4 + ii;
        *(float4*)&Eb[(long)ig * N_ + j0 + tx * 4] = e;
        float rs = e.x + e.y + e.z + e.w;
        // reduce across the 16 tx lanes (xor bits 0..3 stay inside the half-warp)
        rs += __shfl_xor_sync(0xffffffffu, rs, 1);
        rs += __shfl_xor_sync(0xffffffffu, rs, 2);
        rs += __shfl_xor_sync(0xffffffffu, rs, 4);
        rs += __shfl_xor_sync(0xffffffffu, rs, 8);
        if (tx == 0) atomicAdd(&g_D[b * N_ + ig], rs);
    }
}

// ---------------- K2.5: Vp[b,c,i] = Yv[b,c,i] / D[b,i] ----------------------------
__global__ void prescale_kernel()
{
    long idx = (long)blockIdx.x * 256 + threadIdx.x;
    const long total = (long)B_ * C_ * N_;
    if (idx >= total) return;
    int  i    = (int)(idx % N_);
    long rest = idx / N_;
    int  c    = (int)(rest % C_);
    int  b    = (int)(rest / C_);
    float y = g_Y[((long)b * M1_ + 128 + c) * N_ + i];
    g_Vp[idx] = y / g_D[b * N_ + i];
}

// ---------------- launch ----------------------------------------------------------
extern "C" void kernel_launch(void* const* d_in, const int* in_sizes, int n_in,
                              void* d_out, int out_size)
{
    const float* x  = (const float*)d_in[0];
    const float* qw = (const float*)d_in[1];
    const float* qb = (const float*)d_in[2];
    const float* kw = (const float*)d_in[3];
    const float* kb = (const float*)d_in[4];
    const float* vw = (const float*)d_in[5];
    const float* vb = (const float*)d_in[6];
    const float* gw = (const float*)d_in[7];
    const float* gb = (const float*)d_in[8];
    float* out = (float*)d_out;

    void *pW, *pbias, *pY, *pE, *pVp;
    cudaGetSymbolAddress(&pW,    g_W);
    cudaGetSymbolAddress(&pbias, g_bias);
    cudaGetSymbolAddress(&pY,    g_Y);
    cudaGetSymbolAddress(&pE,    g_E);
    cudaGetSymbolAddress(&pVp,   g_Vp);

    // K0: combined weight build (fuses gamma into value projection)
    build_w_kernel<<<M1_, 256>>>(qw, qb, kw, kb, vw, vb, gw);

    // K1: Y = W * x + bias   (per batch: 384x2304 = 384x256 * 256x2304)
    sgemm128_kernel<<<dim3(N_ / 128, M1_ / 128, B_), 256>>>(
        (const float*)pW, x, (float*)pY, (const float*)pbias,
        M1_, N_, C_, 0L, (long)C_ * N_, (long)M1_ * N_);

    // zero row sums
    zero_d_kernel<<<(B_ * N_ + 255) / 256, 256>>>();

    // K2: E = exp(Q^T K), D = row sums
    energy_kernel<<<dim3(N_ / 64, N_ / 64, B_), 256>>>();

    // K2.5: Vp = (G V) / D
    {
        long total = (long)B_ * C_ * N_;
        prescale_kernel<<<(int)((total + 255) / 256), 256>>>();
    }

    // K3: out = Vp * E + gamma_bias   (per batch: 256x2304 = 256x2304 * 2304x2304)
    sgemm128_kernel<<<dim3(N_ / 128, C_ / 128, B_), 256>>>(
        (const float*)pVp, (const float*)pE, out, gb,
        C_, N_, N_, (long)C_ * N_, (long)N_ * N_, (long)C_ * N_);
}

// round 5
// speedup vs baseline: 1.5121x; 1.5121x over previous
#include <cuda_runtime.h>
#include <cuda_bf16.h>
#include <cstdint>

// Problem constants (fixed shapes from reference)
#define B_  8
#define C_  256
#define CK_ 64
#define N_  2304
#define M1_ 384   // combined projection rows: q(64) + k(64) + (gamma@value)(256)

// ---------------- scratch (__device__ globals) ------------------------------------
__device__ float g_W[M1_ * C_];           // combined projection weight
__device__ float g_bias[M1_];             // combined projection bias
__device__ float g_Y[B_ * M1_ * N_];      // q | k | gv  projections
__device__ float g_E[B_ * N_ * N_];       // Et[j][i] = exp(q_i . k_j)  (transposed)
__device__ float g_D[B_ * N_];            // row sums over j, then reciprocals

// ---------------- helpers ----------------------------------------------------------
__device__ __forceinline__ void mma_bf16(float* c,
    uint32_t a0, uint32_t a1, uint32_t a2, uint32_t a3, uint32_t b0, uint32_t b1)
{
    asm volatile(
        "mma.sync.aligned.m16n8k16.row.col.f32.bf16.bf16.f32 "
        "{%0,%1,%2,%3}, {%4,%5,%6,%7}, {%8,%9}, {%0,%1,%2,%3};"
        : "+f"(c[0]), "+f"(c[1]), "+f"(c[2]), "+f"(c[3])
        : "r"(a0), "r"(a1), "r"(a2), "r"(a3), "r"(b0), "r"(b1));
}

// split (a,b) into packed bf16x2 hi + lo planes (low half = a)
__device__ __forceinline__ void split2(float a, float b, uint32_t& hi, uint32_t& lo)
{
    uint32_t h;
    asm("cvt.rn.bf16x2.f32 %0, %1, %2;" : "=r"(h) : "f"(b), "f"(a));
    float ha = __uint_as_float(h << 16);
    float hb = __uint_as_float(h & 0xffff0000u);
    float la = a - ha, lb = b - hb;
    uint32_t l;
    asm("cvt.rn.bf16x2.f32 %0, %1, %2;" : "=r"(l) : "f"(lb), "f"(la));
    hi = h; lo = l;
}

// ---------------- K0: build combined weights --------------------------------------
__global__ __launch_bounds__(256) void build_w_kernel(
    const float* __restrict__ qw, const float* __restrict__ qb,
    const float* __restrict__ kw, const float* __restrict__ kb,
    const float* __restrict__ vw, const float* __restrict__ vb,
    const float* __restrict__ gw)
{
    __shared__ float sg[256];
    int r = blockIdx.x;
    int t = threadIdx.x;
    if (r < 64) {
        g_W[r * C_ + t] = qw[r * C_ + t];
        if (t == 0) g_bias[r] = qb[r];
    } else if (r < 128) {
        g_W[r * C_ + t] = kw[(r - 64) * C_ + t];
        if (t == 0) g_bias[r] = kb[r - 64];
    } else {
        int o = r - 128;
        sg[t] = gw[o * C_ + t];
        __syncthreads();
        float acc = 0.f;
        #pragma unroll 8
        for (int c2 = 0; c2 < C_; c2++)
            acc = fmaf(sg[c2], vw[c2 * C_ + t], acc);
        g_W[r * C_ + t] = acc;
        if (t == 0) {
            float bb = 0.f;
            for (int c2 = 0; c2 < C_; c2++) bb += sg[c2] * vb[c2];
            g_bias[r] = bb;
        }
    }
}

// ---------------- K1: fp32 tiled SGEMM (projection) --------------------------------
__global__ __launch_bounds__(256) void sgemm128_kernel(
    const float* __restrict__ A, const float* __restrict__ Bm,
    float* __restrict__ C, const float* __restrict__ bias,
    int M, int N, int K, long sA, long sB, long sC)
{
    const int b = blockIdx.z;
    const float* Ab = A  + (long)b * sA;
    const float* Bb = Bm + (long)b * sB;
    float*       Cb = C  + (long)b * sC;
    const int bm = blockIdx.y * 128;
    const int bn = blockIdx.x * 128;

    __shared__ float As[16][132];
    __shared__ float Bs[16][128];

    const int tid = threadIdx.x;
    const int tx = tid & 15;
    const int ty = tid >> 4;

    float acc[8][8];
    #pragma unroll
    for (int i = 0; i < 8; i++)
        #pragma unroll
        for (int j = 0; j < 8; j++) acc[i][j] = 0.f;

    for (int kt = 0; kt < K; kt += 16) {
        #pragma unroll
        for (int u = 0; u < 2; u++) {
            int f   = tid + u * 256;
            int row = f >> 2;
            int kk  = (f & 3) * 4;
            float4 a = *(const float4*)&Ab[(long)(bm + row) * K + kt + kk];
            As[kk + 0][row] = a.x;
            As[kk + 1][row] = a.y;
            As[kk + 2][row] = a.z;
            As[kk + 3][row] = a.w;
        }
        #pragma unroll
        for (int u = 0; u < 2; u++) {
            int f    = tid + u * 256;
            int krow = f >> 5;
            int col  = (f & 31) * 4;
            *(float4*)&Bs[krow][col] =
                *(const float4*)&Bb[(long)(kt + krow) * N + bn + col];
        }
        __syncthreads();

        #pragma unroll
        for (int k = 0; k < 16; k++) {
            float a[8], bb[8];
            *(float4*)&a[0]  = *(const float4*)&As[k][ty * 8];
            *(float4*)&a[4]  = *(const float4*)&As[k][ty * 8 + 4];
            *(float4*)&bb[0] = *(const float4*)&Bs[k][tx * 8];
            *(float4*)&bb[4] = *(const float4*)&Bs[k][tx * 8 + 4];
            #pragma unroll
            for (int i = 0; i < 8; i++)
                #pragma unroll
                for (int j = 0; j < 8; j++)
                    acc[i][j] = fmaf(a[i], bb[j], acc[i][j]);
        }
        __syncthreads();
    }

    #pragma unroll
    for (int i = 0; i < 8; i++) {
        int row = bm + ty * 8 + i;
        float bv = bias[row];
        #pragma unroll
        for (int j = 0; j < 8; j += 4) {
            float4 v;
            v.x = acc[i][j + 0] + bv;
            v.y = acc[i][j + 1] + bv;
            v.z = acc[i][j + 2] + bv;
            v.w = acc[i][j + 3] + bv;
            *(float4*)&Cb[(long)row * N + bn + tx * 8 + j] = v;
        }
    }
}

// ---------------- zero / reciprocal D ---------------------------------------------
__global__ void zero_d_kernel() {
    int i = blockIdx.x * 256 + threadIdx.x;
    if (i < B_ * N_) g_D[i] = 0.f;
}
__global__ void rcp_d_kernel() {
    int i = blockIdx.x * 256 + threadIdx.x;
    if (i < B_ * N_) g_D[i] = 1.0f / g_D[i];
}

// ---------------- K2: Et[j,i] = exp(q_i . k_j), D[i] += sums over j ----------------
// 128x128 tile, K=64 resident, 8x8 microtile in two 4-col groups (conflict-free).
#define EQ_STR 132
__global__ __launch_bounds__(256) void energy_kernel()
{
    extern __shared__ float esm[];
    float* qs = esm;                    // [64][132]
    float* ks = esm + 64 * EQ_STR;      // [64][132]
    float* sD = esm + 2 * 64 * EQ_STR;  // [128]

    const int b  = blockIdx.z;
    const int i0 = blockIdx.x * 128;    // query index (cols of Et)
    const int j0 = blockIdx.y * 128;    // key index (rows of Et)
    const float* q  = g_Y + (long)b * M1_ * N_;          // rows [0,64)
    const float* kk = q + (long)CK_ * N_;                // rows [64,128)

    const int tid = threadIdx.x;
    const int tx = tid & 15;            // i direction
    const int ty = tid >> 4;            // j direction

    if (tid < 128) sD[tid] = 0.f;

    #pragma unroll
    for (int u = 0; u < 8; u++) {
        int f    = tid + u * 256;       // 0..2047
        int c    = f >> 5;              // 0..63
        int col  = (f & 31) * 4;        // 0..124
        *(float4*)&qs[c * EQ_STR + col] = *(const float4*)&q [(long)c * N_ + i0 + col];
        *(float4*)&ks[c * EQ_STR + col] = *(const float4*)&kk[(long)c * N_ + j0 + col];
    }
    __syncthreads();

    float acc[8][8];
    #pragma unroll
    for (int jx = 0; jx < 8; jx++)
        #pragma unroll
        for (int ix = 0; ix < 8; ix++) acc[jx][ix] = 0.f;

    #pragma unroll 4
    for (int c = 0; c < 64; c++) {
        float ka[8], qa[8];
        *(float4*)&ka[0] = *(const float4*)&ks[c * EQ_STR + ty * 4];
        *(float4*)&ka[4] = *(const float4*)&ks[c * EQ_STR + 64 + ty * 4];
        *(float4*)&qa[0] = *(const float4*)&qs[c * EQ_STR + tx * 4];
        *(float4*)&qa[4] = *(const float4*)&qs[c * EQ_STR + 64 + tx * 4];
        #pragma unroll
        for (int jx = 0; jx < 8; jx++)
            #pragma unroll
            for (int ix = 0; ix < 8; ix++)
                acc[jx][ix] = fmaf(ka[jx], qa[ix], acc[jx][ix]);
    }

    float* Eb = g_E + (long)b * N_ * N_;
    float psum[8];
    #pragma unroll
    for (int ix = 0; ix < 8; ix++) psum[ix] = 0.f;

    #pragma unroll
    for (int jg = 0; jg < 2; jg++) {
        #pragma unroll
        for (int jj = 0; jj < 4; jj++) {
            int jrow = j0 + jg * 64 + ty * 4 + jj;
            #pragma unroll
            for (int ig = 0; ig < 2; ig++) {
                float4 e;
                e.x = __expf(acc[jg * 4 + jj][ig * 4 + 0]);
                e.y = __expf(acc[jg * 4 + jj][ig * 4 + 1]);
                e.z = __expf(acc[jg * 4 + jj][ig * 4 + 2]);
                e.w = __expf(acc[jg * 4 + jj][ig * 4 + 3]);
                *(float4*)&Eb[(long)jrow * N_ + i0 + ig * 64 + tx * 4] = e;
                psum[ig * 4 + 0] += e.x;
                psum[ig * 4 + 1] += e.y;
                psum[ig * 4 + 2] += e.z;
                psum[ig * 4 + 3] += e.w;
            }
        }
    }

    // reduce ty pairs (lane ^ 16 flips ty LSB, same tx)
    #pragma unroll
    for (int ix = 0; ix < 8; ix++)
        psum[ix] += __shfl_xor_sync(0xffffffffu, psum[ix], 16);
    if ((tid & 16) == 0) {
        #pragma unroll
        for (int ig = 0; ig < 2; ig++)
            #pragma unroll
            for (int m = 0; m < 4; m++)
                atomicAdd(&sD[ig * 64 + tx * 4 + m], psum[ig * 4 + m]);
    }
    __syncthreads();
    if (tid < 128) atomicAdd(&g_D[b * N_ + i0 + tid], sD[tid]);
}

// ---------------- K3: out = (GV/D) * Et^T + gb  via mma.sync bf16 split -------------
// CTA 128(c) x 128(j), k-stage 32, double buffered. warp tile 64x32.
// SMEM per stage: Ahi|Alo|Bhi|Blo, each 128 rows x 32 k bf16, row stride 72B.
#define ST_AHI 0
#define ST_ALO 9216
#define ST_BHI 18432
#define ST_BLO 27648
#define STAGE_ 36864
#define SMEM_K3 (2 * STAGE_)

__global__ void __launch_bounds__(256)
vmul_mma_kernel(float* __restrict__ out, const float* __restrict__ gb)
{
    extern __shared__ char smem[];
    const int tid = threadIdx.x;
    const int lane = tid & 31;
    const int wid  = tid >> 5;
    const int wm = wid >> 2;            // 0..1 -> m offset wm*64
    const int wn = wid & 3;             // 0..3 -> n offset wn*32
    const int b  = blockIdx.z;
    const int c0 = blockIdx.y * 128;
    const int j0 = blockIdx.x * 128;

    const float* Ag = g_Y + ((long)b * M1_ + 128 + c0) * N_;   // GV rows (c), stride N_
    const float* Bg = g_E + (long)b * N_ * N_ + (long)j0 * N_; // Et rows (j), stride N_
    const float* Rg = g_D + b * N_;                            // 1/D per i

    float acc[4][4][4];
    #pragma unroll
    for (int mt = 0; mt < 4; mt++)
        #pragma unroll
        for (int nt = 0; nt < 4; nt++)
            #pragma unroll
            for (int e = 0; e < 4; e++) acc[mt][nt][e] = 0.f;

    const int row0 = tid >> 3;          // 0..31 (+u*32)
    const int q4   = (tid & 7) * 4;     // k element within 32

    float4 ra[4], rb[4], rr;

    // ---- load stage t into regs ----
    auto loadstage = [&](int t) {
        const int kt = t * 32;
        rr = *(const float4*)&Rg[kt + q4];
        #pragma unroll
        for (int u = 0; u < 4; u++) {
            ra[u] = *(const float4*)&Ag[(long)(row0 + u * 32) * N_ + kt + q4];
            rb[u] = *(const float4*)&Bg[(long)(row0 + u * 32) * N_ + kt + q4];
        }
    };

    // ---- convert regs -> smem buffer s ----
    auto storestage = [&](int s) {
        char* buf = smem + s * STAGE_;
        #pragma unroll
        for (int u = 0; u < 4; u++) {
            int row = row0 + u * 32;
            int off = row * 72 + (tid & 7) * 8;
            float4 a = ra[u];
            a.x *= rr.x; a.y *= rr.y; a.z *= rr.z; a.w *= rr.w;   // fold 1/D
            uint32_t h01, l01, h23, l23;
            split2(a.x, a.y, h01, l01);
            split2(a.z, a.w, h23, l23);
            *(uint2*)(buf + ST_AHI + off) = make_uint2(h01, h23);
            *(uint2*)(buf + ST_ALO + off) = make_uint2(l01, l23);
            float4 bv = rb[u];
            split2(bv.x, bv.y, h01, l01);
            split2(bv.z, bv.w, h23, l23);
            *(uint2*)(buf + ST_BHI + off) = make_uint2(h01, h23);
            *(uint2*)(buf + ST_BLO + off) = make_uint2(l01, l23);
        }
    };

    // ---- compute one stage from smem buffer s ----
    const int q  = lane & 3;
    const int r4 = lane >> 2;
    auto compute = [&](int s) {
        const char* buf = smem + s * STAGE_;
        #pragma unroll
        for (int h = 0; h < 2; h++) {
            const int kb = (h * 8 + q) * 4;     // byte offset of k-word
            uint32_t bh[4][2], bl[4][2];
            #pragma unroll
            for (int nt = 0; nt < 4; nt++) {
                int o = (wn * 32 + nt * 8 + r4) * 72 + kb;
                bh[nt][0] = *(const uint32_t*)(buf + ST_BHI + o);
                bh[nt][1] = *(const uint32_t*)(buf + ST_BHI + o + 16);
                bl[nt][0] = *(const uint32_t*)(buf + ST_BLO + o);
                bl[nt][1] = *(const uint32_t*)(buf + ST_BLO + o + 16);
            }
            #pragma unroll
            for (int mt = 0; mt < 4; mt++) {
                int o1 = (wm * 64 + mt * 16 + r4) * 72 + kb;
                int o2 = o1 + 8 * 72;
                uint32_t ah0 = *(const uint32_t*)(buf + ST_AHI + o1);
                uint32_t ah1 = *(const uint32_t*)(buf + ST_AHI + o2);
                uint32_t ah2 = *(const uint32_t*)(buf + ST_AHI + o1 + 16);
                uint32_t ah3 = *(const uint32_t*)(buf + ST_AHI + o2 + 16);
                uint32_t al0 = *(const uint32_t*)(buf + ST_ALO + o1);
                uint32_t al1 = *(const uint32_t*)(buf + ST_ALO + o2);
                uint32_t al2 = *(const uint32_t*)(buf + ST_ALO + o1 + 16);
                uint32_t al3 = *(const uint32_t*)(buf + ST_ALO + o2 + 16);
                #pragma unroll
                for (int nt = 0; nt < 4; nt++) {
                    mma_bf16(acc[mt][nt], ah0, ah1, ah2, ah3, bh[nt][0], bh[nt][1]);
                    mma_bf16(acc[mt][nt], ah0, ah1, ah2, ah3, bl[nt][0], bl[nt][1]);
                    mma_bf16(acc[mt][nt], al0, al1, al2, al3, bh[nt][0], bh[nt][1]);
                }
            }
        }
    };

    loadstage(0);
    storestage(0);
    __syncthreads();

    for (int t = 0; t < 72; t++) {
        if (t < 71) loadstage(t + 1);
        compute(t & 1);
        __syncthreads();
        if (t < 71) {
            storestage((t + 1) & 1);
            __syncthreads();
        }
    }

    // epilogue: c-frag c0,c1 at (r4, 2q(+1)); c2,c3 at (r4+8, 2q(+1))
    #pragma unroll
    for (int mt = 0; mt < 4; mt++) {
        int rA = c0 + wm * 64 + mt * 16 + r4;
        float bv0 = gb[rA];
        float bv8 = gb[rA + 8];
        #pragma unroll
        for (int nt = 0; nt < 4; nt++) {
            int col = j0 + wn * 32 + nt * 8 + q * 2;
            float2 v0, v1;
            v0.x = acc[mt][nt][0] + bv0;
            v0.y = acc[mt][nt][1] + bv0;
            v1.x = acc[mt][nt][2] + bv8;
            v1.y = acc[mt][nt][3] + bv8;
            *(float2*)&out[((long)b * C_ + rA) * N_ + col]     = v0;
            *(float2*)&out[((long)b * C_ + rA + 8) * N_ + col] = v1;
        }
    }
}

// ---------------- launch ----------------------------------------------------------
extern "C" void kernel_launch(void* const* d_in, const int* in_sizes, int n_in,
                              void* d_out, int out_size)
{
    const float* x  = (const float*)d_in[0];
    const float* qw = (const float*)d_in[1];
    const float* qb = (const float*)d_in[2];
    const float* kw = (const float*)d_in[3];
    const float* kb = (const float*)d_in[4];
    const float* vw = (const float*)d_in[5];
    const float* vb = (const float*)d_in[6];
    const float* gw = (const float*)d_in[7];
    const float* gb = (const float*)d_in[8];
    float* out = (float*)d_out;

    void *pW, *pbias, *pY;
    cudaGetSymbolAddress(&pW,    g_W);
    cudaGetSymbolAddress(&pbias, g_bias);
    cudaGetSymbolAddress(&pY,    g_Y);

    const int esmem = (2 * 64 * EQ_STR + 128) * sizeof(float);
    cudaFuncSetAttribute(energy_kernel,
                         cudaFuncAttributeMaxDynamicSharedMemorySize, esmem);
    cudaFuncSetAttribute(vmul_mma_kernel,
                         cudaFuncAttributeMaxDynamicSharedMemorySize, SMEM_K3);

    // K0: combined weight build (gamma folded into value projection)
    build_w_kernel<<<M1_, 256>>>(qw, qb, kw, kb, vw, vb, gw);

    // K1: Y = W * x + bias   (per batch: 384x2304 = 384x256 * 256x2304)
    sgemm128_kernel<<<dim3(N_ / 128, M1_ / 128, B_), 256>>>(
        (const float*)pW, x, (float*)pY, (const float*)pbias,
        M1_, N_, C_, 0L, (long)C_ * N_, (long)M1_ * N_);

    // zero row sums
    zero_d_kernel<<<(B_ * N_ + 255) / 256, 256>>>();

    // K2: Et = exp(Q^T K) transposed, D = per-query sums
    energy_kernel<<<dim3(N_ / 128, N_ / 128, B_), 256, esmem>>>();

    // D -> 1/D
    rcp_d_kernel<<<(B_ * N_ + 255) / 256, 256>>>();

    // K3: out[c,j] = sum_i (GV[c,i]/D[i]) * Et[j,i] + gb[c]   (HMMA bf16 split)
    vmul_mma_kernel<<<dim3(N_ / 128, C_ / 128, B_), 256, SMEM_K3>>>(out, gb);
}

// round 8
// speedup vs baseline: 1.6347x; 1.0811x over previous
#include <cuda_runtime.h>
#include <cuda_bf16.h>
#include <cstdint>

// Problem constants (fixed shapes from reference)
#define B_  8
#define C_  256
#define CK_ 64
#define N_  2304
#define M1_ 384   // combined projection rows: q(64) + k(64) + (gamma@value)(256)

// ---------------- scratch (__device__ globals) ------------------------------------
__device__ float g_W[M1_ * C_];                     // combined projection weight
__device__ float g_bias[M1_];                       // combined projection bias
__device__ float g_Y[B_ * M1_ * N_];                // q | k | gv  projections
__device__ unsigned short g_Ehi[B_ * (long)N_ * N_]; // exp(QK) hi bf16 plane [b][j][i]
__device__ unsigned short g_Elo[B_ * (long)N_ * N_]; // exp(QK) lo bf16 plane
__device__ unsigned short g_Ahi[B_ * C_ * N_];      // (GV/D) hi bf16 plane [b][c][i]
__device__ unsigned short g_Alo[B_ * C_ * N_];      // (GV/D) lo bf16 plane
__device__ float g_D[B_ * N_];                      // row sums over j, then reciprocals

// ---------------- helpers ----------------------------------------------------------
__device__ __forceinline__ void mma_bf16(float* c,
    uint32_t a0, uint32_t a1, uint32_t a2, uint32_t a3, uint32_t b0, uint32_t b1)
{
    asm volatile(
        "mma.sync.aligned.m16n8k16.row.col.f32.bf16.bf16.f32 "
        "{%0,%1,%2,%3}, {%4,%5,%6,%7}, {%8,%9}, {%0,%1,%2,%3};"
        : "+f"(c[0]), "+f"(c[1]), "+f"(c[2]), "+f"(c[3])
        : "r"(a0), "r"(a1), "r"(a2), "r"(a3), "r"(b0), "r"(b1));
}

// split (a,b) into packed bf16x2 hi + lo planes (low half = a)
__device__ __forceinline__ void split2(float a, float b, uint32_t& hi, uint32_t& lo)
{
    uint32_t h;
    asm("cvt.rn.bf16x2.f32 %0, %1, %2;" : "=r"(h) : "f"(b), "f"(a));
    float ha = __uint_as_float(h << 16);
    float hb = __uint_as_float(h & 0xffff0000u);
    float la = a - ha, lb = b - hb;
    uint32_t l;
    asm("cvt.rn.bf16x2.f32 %0, %1, %2;" : "=r"(l) : "f"(lb), "f"(la));
    hi = h; lo = l;
}

__device__ __forceinline__ uint32_t smem_u32(const void* p) {
    uint32_t a;
    asm("{ .reg .u64 t; cvta.to.shared.u64 t, %1; cvt.u32.u64 %0, t; }" : "=r"(a) : "l"(p));
    return a;
}
__device__ __forceinline__ void cp16(uint32_t dst, const void* src) {
    asm volatile("cp.async.cg.shared.global [%0], [%1], 16;" :: "r"(dst), "l"(src));
}
#define CP_COMMIT() asm volatile("cp.async.commit_group;" ::: "memory")
#define CP_WAIT(n)  asm volatile("cp.async.wait_group %0;" :: "n"(n) : "memory")

// ---------------- K0: build combined weights --------------------------------------
__global__ __launch_bounds__(256) void build_w_kernel(
    const float* __restrict__ qw, const float* __restrict__ qb,
    const float* __restrict__ kw, const float* __restrict__ kb,
    const float* __restrict__ vw, const float* __restrict__ vb,
    const float* __restrict__ gw)
{
    __shared__ float sg[256];
    int r = blockIdx.x;
    int t = threadIdx.x;
    if (r < 64) {
        g_W[r * C_ + t] = qw[r * C_ + t];
        if (t == 0) g_bias[r] = qb[r];
    } else if (r < 128) {
        g_W[r * C_ + t] = kw[(r - 64) * C_ + t];
        if (t == 0) g_bias[r] = kb[r - 64];
    } else {
        int o = r - 128;
        sg[t] = gw[o * C_ + t];
        __syncthreads();
        float acc = 0.f;
        #pragma unroll 8
        for (int c2 = 0; c2 < C_; c2++)
            acc = fmaf(sg[c2], vw[c2 * C_ + t], acc);
        g_W[r * C_ + t] = acc;
        if (t == 0) {
            float bb = 0.f;
            for (int c2 = 0; c2 < C_; c2++) bb += sg[c2] * vb[c2];
            g_bias[r] = bb;
        }
    }
}

// ---------------- K1: fp32 tiled SGEMM (projection) --------------------------------
__global__ __launch_bounds__(256) void sgemm128_kernel(
    const float* __restrict__ A, const float* __restrict__ Bm,
    float* __restrict__ C, const float* __restrict__ bias,
    int M, int N, int K, long sA, long sB, long sC)
{
    const int b = blockIdx.z;
    const float* Ab = A  + (long)b * sA;
    const float* Bb = Bm + (long)b * sB;
    float*       Cb = C  + (long)b * sC;
    const int bm = blockIdx.y * 128;
    const int bn = blockIdx.x * 128;

    __shared__ float As[16][132];
    __shared__ float Bs[16][128];

    const int tid = threadIdx.x;
    const int tx = tid & 15;
    const int ty = tid >> 4;

    float acc[8][8];
    #pragma unroll
    for (int i = 0; i < 8; i++)
        #pragma unroll
        for (int j = 0; j < 8; j++) acc[i][j] = 0.f;

    for (int kt = 0; kt < K; kt += 16) {
        #pragma unroll
        for (int u = 0; u < 2; u++) {
            int f   = tid + u * 256;
            int row = f >> 2;
            int kk  = (f & 3) * 4;
            float4 a = *(const float4*)&Ab[(long)(bm + row) * K + kt + kk];
            As[kk + 0][row] = a.x;
            As[kk + 1][row] = a.y;
            As[kk + 2][row] = a.z;
            As[kk + 3][row] = a.w;
        }
        #pragma unroll
        for (int u = 0; u < 2; u++) {
            int f    = tid + u * 256;
            int krow = f >> 5;
            int col  = (f & 31) * 4;
            *(float4*)&Bs[krow][col] =
                *(const float4*)&Bb[(long)(kt + krow) * N + bn + col];
        }
        __syncthreads();

        #pragma unroll
        for (int k = 0; k < 16; k++) {
            float a[8], bb[8];
            *(float4*)&a[0]  = *(const float4*)&As[k][ty * 8];
            *(float4*)&a[4]  = *(const float4*)&As[k][ty * 8 + 4];
            *(float4*)&bb[0] = *(const float4*)&Bs[k][tx * 8];
            *(float4*)&bb[4] = *(const float4*)&Bs[k][tx * 8 + 4];
            #pragma unroll
            for (int i = 0; i < 8; i++)
                #pragma unroll
                for (int j = 0; j < 8; j++)
                    acc[i][j] = fmaf(a[i], bb[j], acc[i][j]);
        }
        __syncthreads();
    }

    #pragma unroll
    for (int i = 0; i < 8; i++) {
        int row = bm + ty * 8 + i;
        float bv = bias[row];
        #pragma unroll
        for (int j = 0; j < 8; j += 4) {
            float4 v;
            v.x = acc[i][j + 0] + bv;
            v.y = acc[i][j + 1] + bv;
            v.z = acc[i][j + 2] + bv;
            v.w = acc[i][j + 3] + bv;
            *(float4*)&Cb[(long)row * N + bn + tx * 8 + j] = v;
        }
    }
}

// ---------------- zero / reciprocal D ---------------------------------------------
__global__ void zero_d_kernel() {
    int i = blockIdx.x * 256 + threadIdx.x;
    if (i < B_ * N_) g_D[i] = 0.f;
}
__global__ void rcp_d_kernel() {
    int i = blockIdx.x * 256 + threadIdx.x;
    if (i < B_ * N_) g_D[i] = 1.0f / g_D[i];
}

// ---------------- K2: Ehi/Elo[j,i] = split(exp(q_i . k_j)), D[i] += sums -----------
#define EQ_STR 132
__global__ __launch_bounds__(256) void energy_kernel()
{
    extern __shared__ float esm[];
    float* qs = esm;                    // [64][132]
    float* ks = esm + 64 * EQ_STR;      // [64][132]
    float* sD = esm + 2 * 64 * EQ_STR;  // [128]

    const int b  = blockIdx.z;
    const int i0 = blockIdx.x * 128;    // query index (cols of Et)
    const int j0 = blockIdx.y * 128;    // key index (rows of Et)
    const float* q  = g_Y + (long)b * M1_ * N_;          // rows [0,64)
    const float* kk = q + (long)CK_ * N_;                // rows [64,128)

    const int tid = threadIdx.x;
    const int tx = tid & 15;            // i direction
    const int ty = tid >> 4;            // j direction

    if (tid < 128) sD[tid] = 0.f;

    #pragma unroll
    for (int u = 0; u < 8; u++) {
        int f    = tid + u * 256;       // 0..2047
        int c    = f >> 5;              // 0..63
        int col  = (f & 31) * 4;        // 0..124
        *(float4*)&qs[c * EQ_STR + col] = *(const float4*)&q [(long)c * N_ + i0 + col];
        *(float4*)&ks[c * EQ_STR + col] = *(const float4*)&kk[(long)c * N_ + j0 + col];
    }
    __syncthreads();

    float acc[8][8];
    #pragma unroll
    for (int jx = 0; jx < 8; jx++)
        #pragma unroll
        for (int ix = 0; ix < 8; ix++) acc[jx][ix] = 0.f;

    #pragma unroll 4
    for (int c = 0; c < 64; c++) {
        float ka[8], qa[8];
        *(float4*)&ka[0] = *(const float4*)&ks[c * EQ_STR + ty * 4];
        *(float4*)&ka[4] = *(const float4*)&ks[c * EQ_STR + 64 + ty * 4];
        *(float4*)&qa[0] = *(const float4*)&qs[c * EQ_STR + tx * 4];
        *(float4*)&qa[4] = *(const float4*)&qs[c * EQ_STR + 64 + tx * 4];
        #pragma unroll
        for (int jx = 0; jx < 8; jx++)
            #pragma unroll
            for (int ix = 0; ix < 8; ix++)
                acc[jx][ix] = fmaf(ka[jx], qa[ix], acc[jx][ix]);
    }

    float psum[8];
    #pragma unroll
    for (int ix = 0; ix < 8; ix++) psum[ix] = 0.f;

    #pragma unroll
    for (int jg = 0; jg < 2; jg++) {
        #pragma unroll
        for (int jj = 0; jj < 4; jj++) {
            long jrow = j0 + jg * 64 + ty * 4 + jj;
            #pragma unroll
            for (int ig = 0; ig < 2; ig++) {
                float4 e;
                e.x = __expf(acc[jg * 4 + jj][ig * 4 + 0]);
                e.y = __expf(acc[jg * 4 + jj][ig * 4 + 1]);
                e.z = __expf(acc[jg * 4 + jj][ig * 4 + 2]);
                e.w = __expf(acc[jg * 4 + jj][ig * 4 + 3]);
                uint32_t h01, l01, h23, l23;
                split2(e.x, e.y, h01, l01);
                split2(e.z, e.w, h23, l23);
                long idx = ((long)b * N_ + jrow) * N_ + i0 + ig * 64 + tx * 4;
                *(uint2*)&g_Ehi[idx] = make_uint2(h01, h23);
                *(uint2*)&g_Elo[idx] = make_uint2(l01, l23);
                psum[ig * 4 + 0] += e.x;
                psum[ig * 4 + 1] += e.y;
                psum[ig * 4 + 2] += e.z;
                psum[ig * 4 + 3] += e.w;
            }
        }
    }

    // reduce ty pairs (lane ^ 16 flips ty LSB, same tx)
    #pragma unroll
    for (int ix = 0; ix < 8; ix++)
        psum[ix] += __shfl_xor_sync(0xffffffffu, psum[ix], 16);
    if ((tid & 16) == 0) {
        #pragma unroll
        for (int ig = 0; ig < 2; ig++)
            #pragma unroll
            for (int m = 0; m < 4; m++)
                atomicAdd(&sD[ig * 64 + tx * 4 + m], psum[ig * 4 + m]);
    }
    __syncthreads();
    if (tid < 128) atomicAdd(&g_D[b * N_ + i0 + tid], sD[tid]);
}

// ---------------- K2.5: A planes: (GV * 1/D) -> bf16 hi/lo -------------------------
__global__ __launch_bounds__(256) void prescale_kernel()
{
    long idx4 = (long)blockIdx.x * 256 + threadIdx.x;     // one float4 each
    const long total4 = (long)B_ * C_ * N_ / 4;
    if (idx4 >= total4) return;
    long e0   = idx4 * 4;
    int  i    = (int)(e0 % N_);
    long rest = e0 / N_;
    int  c    = (int)(rest % C_);
    int  b    = (int)(rest / C_);
    float4 y  = *(const float4*)&g_Y[((long)b * M1_ + 128 + c) * N_ + i];
    float4 rr = *(const float4*)&g_D[b * N_ + i];          // 1/D
    y.x *= rr.x; y.y *= rr.y; y.z *= rr.z; y.w *= rr.w;
    uint32_t h01, l01, h23, l23;
    split2(y.x, y.y, h01, l01);
    split2(y.z, y.w, h23, l23);
    *(uint2*)&g_Ahi[e0] = make_uint2(h01, h23);
    *(uint2*)&g_Alo[e0] = make_uint2(l01, l23);
}

// ---------------- K3: out = A * Et^T + gb  (pure bf16 3-term, cp.async pipeline) ---
// CTA 128(c) x 128(j), k-stage 32, depth-2 pipeline. warp tile 64x32.
// SMEM per stage: Ahi|Alo|Bhi|Blo, each 128 rows x 32 k bf16, row stride 80B
// (16B-aligned for cp.async; bank-conflict-free: word idx = r4*20+q covers 32 banks).
#define PL_SZ  10240              // 128 rows * 80B
#define ST_AHI 0
#define ST_ALO (1 * PL_SZ)
#define ST_BHI (2 * PL_SZ)
#define ST_BLO (3 * PL_SZ)
#define STAGE_ (4 * PL_SZ)        // 40960
#define DEPTH_ 2
#define SMEM_K3 (DEPTH_ * STAGE_) // 81920 -> 2 CTAs/SM fits 228KB carveout

__global__ void __launch_bounds__(256, 2)
vmul_mma_kernel(float* __restrict__ out, const float* __restrict__ gb)
{
    extern __shared__ char smem[];
    const uint32_t sbase = smem_u32(smem);
    const int tid = threadIdx.x;
    const int lane = tid & 31;
    const int wid  = tid >> 5;
    const int wm = wid >> 2;            // 0..1 -> m offset wm*64
    const int wn = wid & 3;             // 0..3 -> n offset wn*32
    const int b  = blockIdx.z;
    const int c0 = blockIdx.y * 128;
    const int j0 = blockIdx.x * 128;

    // per-thread cp.async assignment: plane p, 8 chunks of 16B
    const int p   = tid >> 6;           // 0..3: Ahi, Alo, Bhi, Blo
    const int t64 = tid & 63;
    const unsigned short* gsrc;
    long rowbase;
    if (p == 0)      { gsrc = g_Ahi; rowbase = (long)b * C_ + c0; }
    else if (p == 1) { gsrc = g_Alo; rowbase = (long)b * C_ + c0; }
    else if (p == 2) { gsrc = g_Ehi; rowbase = (long)b * N_ + j0; }
    else             { gsrc = g_Elo; rowbase = (long)b * N_ + j0; }
    const uint32_t pdst = sbase + p * PL_SZ;

    auto issue = [&](int t, int s) {
        const int kt = t * 32;
        const uint32_t d0 = pdst + s * STAGE_;
        #pragma unroll
        for (int u = 0; u < 8; u++) {
            int cid = u * 64 + t64;     // 0..511
            int row = cid >> 2;
            int c4  = cid & 3;
            cp16(d0 + row * 80 + c4 * 16,
                 gsrc + (rowbase + row) * N_ + kt + c4 * 8);
        }
        CP_COMMIT();
    };

    float acc[4][4][4];
    #pragma unroll
    for (int mt = 0; mt < 4; mt++)
        #pragma unroll
        for (int nt = 0; nt < 4; nt++)
            #pragma unroll
            for (int e = 0; e < 4; e++) acc[mt][nt][e] = 0.f;

    const int q  = lane & 3;
    const int r4 = lane >> 2;
    auto compute = [&](int s) {
        const char* buf = smem + s * STAGE_;
        #pragma unroll
        for (int h = 0; h < 2; h++) {
            const int kb = (h * 8 + q) * 4;     // byte offset of k-word
            uint32_t bh[4][2], bl[4][2];
            #pragma unroll
            for (int nt = 0; nt < 4; nt++) {
                int o = (wn * 32 + nt * 8 + r4) * 80 + kb;
                bh[nt][0] = *(const uint32_t*)(buf + ST_BHI + o);
                bh[nt][1] = *(const uint32_t*)(buf + ST_BHI + o + 16);
                bl[nt][0] = *(const uint32_t*)(buf + ST_BLO + o);
                bl[nt][1] = *(const uint32_t*)(buf + ST_BLO + o + 16);
            }
            #pragma unroll
            for (int mt = 0; mt < 4; mt++) {
                int o1 = (wm * 64 + mt * 16 + r4) * 80 + kb;
                int o2 = o1 + 8 * 80;
                uint32_t ah0 = *(const uint32_t*)(buf + ST_AHI + o1);
                uint32_t ah1 = *(const uint32_t*)(buf + ST_AHI + o2);
                uint32_t ah2 = *(const uint32_t*)(buf + ST_AHI + o1 + 16);
                uint32_t ah3 = *(const uint32_t*)(buf + ST_AHI + o2 + 16);
                uint32_t al0 = *(const uint32_t*)(buf + ST_ALO + o1);
                uint32_t al1 = *(const uint32_t*)(buf + ST_ALO + o2);
                uint32_t al2 = *(const uint32_t*)(buf + ST_ALO + o1 + 16);
                uint32_t al3 = *(const uint32_t*)(buf + ST_ALO + o2 + 16);
                #pragma unroll
                for (int nt = 0; nt < 4; nt++) {
                    mma_bf16(acc[mt][nt], ah0, ah1, ah2, ah3, bh[nt][0], bh[nt][1]);
                    mma_bf16(acc[mt][nt], ah0, ah1, ah2, ah3, bl[nt][0], bl[nt][1]);
                    mma_bf16(acc[mt][nt], al0, al1, al2, al3, bh[nt][0], bh[nt][1]);
                }
            }
        }
    };

    // prologue: fill stage 0
    issue(0, 0);

    for (int t = 0; t < 72; t++) {
        if (t + 1 < 72) issue(t + 1, (t + 1) & 1);
        else CP_COMMIT();               // keep group accounting in sync
        CP_WAIT(1);                     // oldest group (stage t) complete
        __syncthreads();
        compute(t & 1);
        __syncthreads();
    }

    // epilogue: c-frag c0,c1 at (r4, 2q(+1)); c2,c3 at (r4+8, 2q(+1))
    #pragma unroll
    for (int mt = 0; mt < 4; mt++) {
        int rA = c0 + wm * 64 + mt * 16 + r4;
        float bv0 = gb[rA];
        float bv8 = gb[rA + 8];
        #pragma unroll
        for (int nt = 0; nt < 4; nt++) {
            int col = j0 + wn * 32 + nt * 8 + q * 2;
            float2 v0, v1;
            v0.x = acc[mt][nt][0] + bv0;
            v0.y = acc[mt][nt][1] + bv0;
            v1.x = acc[mt][nt][2] + bv8;
            v1.y = acc[mt][nt][3] + bv8;
            *(float2*)&out[((long)b * C_ + rA) * N_ + col]     = v0;
            *(float2*)&out[((long)b * C_ + rA + 8) * N_ + col] = v1;
        }
    }
}

// ---------------- launch ----------------------------------------------------------
extern "C" void kernel_launch(void* const* d_in, const int* in_sizes, int n_in,
                              void* d_out, int out_size)
{
    const float* x  = (const float*)d_in[0];
    const float* qw = (const float*)d_in[1];
    const float* qb = (const float*)d_in[2];
    const float* kw = (const float*)d_in[3];
    const float* kb = (const float*)d_in[4];
    const float* vw = (const float*)d_in[5];
    const float* vb = (const float*)d_in[6];
    const float* gw = (const float*)d_in[7];
    const float* gb = (const float*)d_in[8];
    float* out = (float*)d_out;

    void *pW, *pbias, *pY;
    cudaGetSymbolAddress(&pW,    g_W);
    cudaGetSymbolAddress(&pbias, g_bias);
    cudaGetSymbolAddress(&pY,    g_Y);

    const int esmem = (2 * 64 * EQ_STR + 128) * sizeof(float);
    cudaFuncSetAttribute(energy_kernel,
                         cudaFuncAttributeMaxDynamicSharedMemorySize, esmem);
    cudaFuncSetAttribute(vmul_mma_kernel,
                         cudaFuncAttributeMaxDynamicSharedMemorySize, SMEM_K3);

    // K0: combined weight build (gamma folded into value projection)
    build_w_kernel<<<M1_, 256>>>(qw, qb, kw, kb, vw, vb, gw);

    // K1: Y = W * x + bias   (per batch: 384x2304 = 384x256 * 256x2304)
    sgemm128_kernel<<<dim3(N_ / 128, M1_ / 128, B_), 256>>>(
        (const float*)pW, x, (float*)pY, (const float*)pbias,
        M1_, N_, C_, 0L, (long)C_ * N_, (long)M1_ * N_);

    // zero row sums
    zero_d_kernel<<<(B_ * N_ + 255) / 256, 256>>>();

    // K2: Ehi/Elo = split(exp(Q^T K)) transposed, D = per-query sums
    energy_kernel<<<dim3(N_ / 128, N_ / 128, B_), 256, esmem>>>();

    // D -> 1/D
    rcp_d_kernel<<<(B_ * N_ + 255) / 256, 256>>>();

    // K2.5: A planes = split(GV * 1/D)
    {
        long total4 = (long)B_ * C_ * N_ / 4;
        prescale_kernel<<<(int)((total4 + 255) / 256), 256>>>();
    }

    // K3: out[c,j] = sum_i A[c,i] * Et[j,i] + gb[c]   (bf16 3-term MMA, cp.async)
    vmul_mma_kernel<<<dim3(N_ / 128, C_ / 128, B_), 256, SMEM_K3>>>(out, gb);
}

// round 9
// speedup vs baseline: 1.9738x; 1.2075x over previous
#include <cuda_runtime.h>
#include <cuda_bf16.h>
#include <cstdint>

// Problem constants (fixed shapes from reference)
#define B_  8
#define C_  256
#define CK_ 64
#define N_  2304

typedef unsigned short u16;

// ---------------- scratch (__device__ globals) ------------------------------------
__device__ u16   g_xthi[B_ * N_ * C_];        // x transposed [b][n][c], bf16 hi
__device__ u16   g_xtlo[B_ * N_ * C_];        // lo plane
__device__ u16   g_Wqkhi[128 * C_];           // q(64)+k(64) weights [ck][c]
__device__ u16   g_Wqklo[128 * C_];
__device__ u16   g_Wgvhi[C_ * C_];            // (gamma@value) weights [c_out][c]
__device__ u16   g_Wgvlo[C_ * C_];
__device__ float g_biasA[384];                // qb|kb|gv bias
__device__ u16   g_QKthi[B_ * N_ * 128];      // Qt|Kt [b][i][ck] bf16 hi
__device__ u16   g_QKtlo[B_ * N_ * 128];
__device__ float g_Ygv[B_ * C_ * N_];         // GV projection fp32 [b][c][i]
__device__ u16   g_Ehi[(long)B_ * N_ * N_];   // exp(QK) [b][j][i] hi plane
__device__ u16   g_Elo[(long)B_ * N_ * N_];
__device__ u16   g_Ahi[B_ * C_ * N_];         // (GV/D) [b][c][i] hi plane
__device__ u16   g_Alo[B_ * C_ * N_];
__device__ float g_D[B_ * N_];                // row sums over j, then reciprocals

// ---------------- helpers ----------------------------------------------------------
__device__ __forceinline__ void mma_bf16(float* c,
    uint32_t a0, uint32_t a1, uint32_t a2, uint32_t a3, uint32_t b0, uint32_t b1)
{
    asm volatile(
        "mma.sync.aligned.m16n8k16.row.col.f32.bf16.bf16.f32 "
        "{%0,%1,%2,%3}, {%4,%5,%6,%7}, {%8,%9}, {%0,%1,%2,%3};"
        : "+f"(c[0]), "+f"(c[1]), "+f"(c[2]), "+f"(c[3])
        : "r"(a0), "r"(a1), "r"(a2), "r"(a3), "r"(b0), "r"(b1));
}

// split (a,b) into packed bf16x2 hi + lo planes (low half = a)
__device__ __forceinline__ void split2(float a, float b, uint32_t& hi, uint32_t& lo)
{
    uint32_t h;
    asm("cvt.rn.bf16x2.f32 %0, %1, %2;" : "=r"(h) : "f"(b), "f"(a));
    float ha = __uint_as_float(h << 16);
    float hb = __uint_as_float(h & 0xffff0000u);
    float la = a - ha, lb = b - hb;
    uint32_t l;
    asm("cvt.rn.bf16x2.f32 %0, %1, %2;" : "=r"(l) : "f"(lb), "f"(la));
    hi = h; lo = l;
}

__device__ __forceinline__ uint32_t smem_u32(const void* p) {
    uint32_t a;
    asm("{ .reg .u64 t; cvta.to.shared.u64 t, %1; cvt.u32.u64 %0, t; }" : "=r"(a) : "l"(p));
    return a;
}
__device__ __forceinline__ void cp16(uint32_t dst, const void* src) {
    asm volatile("cp.async.cg.shared.global [%0], [%1], 16;" :: "r"(dst), "l"(src));
}
#define CP_COMMIT() asm volatile("cp.async.commit_group;" ::: "memory")
#define CP_WAIT(n)  asm volatile("cp.async.wait_group %0;" :: "n"(n) : "memory")

// ---------------- K0: build weights (split planes; gamma folded into value) -------
__global__ __launch_bounds__(256) void build_w_kernel(
    const float* __restrict__ qw, const float* __restrict__ qb,
    const float* __restrict__ kw, const float* __restrict__ kb,
    const float* __restrict__ vw, const float* __restrict__ vb,
    const float* __restrict__ gw)
{
    __shared__ float sg[256];
    __shared__ float srow[256];
    int r = blockIdx.x;
    int t = threadIdx.x;
    if (r < 64) {
        if (t < 128) {
            uint32_t h, l;
            split2(qw[r * C_ + 2 * t], qw[r * C_ + 2 * t + 1], h, l);
            *(uint32_t*)&g_Wqkhi[r * C_ + 2 * t] = h;
            *(uint32_t*)&g_Wqklo[r * C_ + 2 * t] = l;
        }
        if (t == 0) g_biasA[r] = qb[r];
    } else if (r < 128) {
        if (t < 128) {
            uint32_t h, l;
            split2(kw[(r - 64) * C_ + 2 * t], kw[(r - 64) * C_ + 2 * t + 1], h, l);
            *(uint32_t*)&g_Wqkhi[r * C_ + 2 * t] = h;
            *(uint32_t*)&g_Wqklo[r * C_ + 2 * t] = l;
        }
        if (t == 0) g_biasA[r] = kb[r - 64];
    } else {
        int o = r - 128;
        sg[t] = gw[o * C_ + t];
        __syncthreads();
        float acc = 0.f;
        #pragma unroll 8
        for (int c2 = 0; c2 < C_; c2++)
            acc = fmaf(sg[c2], vw[c2 * C_ + t], acc);
        srow[t] = acc;
        if (t == 0) {
            float bb = 0.f;
            for (int c2 = 0; c2 < C_; c2++) bb += sg[c2] * vb[c2];
            g_biasA[r] = bb;
        }
        __syncthreads();
        if (t < 128) {
            uint32_t h, l;
            split2(srow[2 * t], srow[2 * t + 1], h, l);
            *(uint32_t*)&g_Wgvhi[o * C_ + 2 * t] = h;
            *(uint32_t*)&g_Wgvlo[o * C_ + 2 * t] = l;
        }
    }
}

// ---------------- xsplit: x[b][c][n] fp32 -> xt[b][n][c] bf16 hi/lo ----------------
__global__ __launch_bounds__(256) void xsplit_kernel(const float* __restrict__ x)
{
    __shared__ float sm[64][65];
    const int b = blockIdx.z, c0 = blockIdx.y * 64, n0 = blockIdx.x * 64;
    const int tid = threadIdx.x;
    const float* xb = x + ((long)b * C_ + c0) * N_ + n0;
    #pragma unroll
    for (int u = 0; u < 4; u++) {
        int f  = tid + u * 256;     // 0..1023
        int c  = f >> 4;            // 0..63
        int n4 = (f & 15) * 4;
        float4 v = *(const float4*)&xb[(long)c * N_ + n4];
        sm[c][n4 + 0] = v.x; sm[c][n4 + 1] = v.y;
        sm[c][n4 + 2] = v.z; sm[c][n4 + 3] = v.w;
    }
    __syncthreads();
    const int nl  = tid & 63;
    const int c16 = (tid >> 6) * 16;
    long obase = ((long)b * N_ + n0 + nl) * C_ + c0 + c16;
    uint32_t hw[8], lw[8];
    #pragma unroll
    for (int m = 0; m < 8; m++)
        split2(sm[c16 + 2 * m][nl], sm[c16 + 2 * m + 1][nl], hw[m], lw[m]);
    *(uint4*)&g_xthi[obase]     = make_uint4(hw[0], hw[1], hw[2], hw[3]);
    *(uint4*)&g_xthi[obase + 8] = make_uint4(hw[4], hw[5], hw[6], hw[7]);
    *(uint4*)&g_xtlo[obase]     = make_uint4(lw[0], lw[1], lw[2], lw[3]);
    *(uint4*)&g_xtlo[obase + 8] = make_uint4(lw[4], lw[5], lw[6], lw[7]);
}

// ---------------- zero / reciprocal D ---------------------------------------------
__global__ void zero_d_kernel() {
    int i = blockIdx.x * 256 + threadIdx.x;
    if (i < B_ * N_) g_D[i] = 0.f;
}
__global__ void rcp_d_kernel() {
    int i = blockIdx.x * 256 + threadIdx.x;
    if (i < B_ * N_) g_D[i] = 1.0f / g_D[i];
}

// ---------------- generalized 3-term bf16 MMA GEMM (cp.async, depth-2) -------------
// out[m][n] = sum_k (Ahi+Alo)[m][k] * (Bhi+Blo)[n][k]  (drops lo*lo)
// mode 0: fp32 out + per-m bias.  mode 1: split bf16 hi/lo out + per-n bias.
#define PL_SZ  10240              // 128 rows * 80B
#define ST_AHI 0
#define ST_ALO (1 * PL_SZ)
#define ST_BHI (2 * PL_SZ)
#define ST_BLO (3 * PL_SZ)
#define STAGE_ (4 * PL_SZ)        // 40960
#define SMEM_G (2 * STAGE_)       // 81920 -> 2 CTAs/SM

__global__ void __launch_bounds__(256, 2)
gemm3_kernel(int kstages, int mode,
             const u16* __restrict__ Ahi, const u16* __restrict__ Alo,
             int arows, int astr,
             const u16* __restrict__ Bhi, const u16* __restrict__ Blo,
             int brows, int bstr,
             float* __restrict__ outF, u16* __restrict__ oHi, u16* __restrict__ oLo,
             int orows, int ostr, const float* __restrict__ bias)
{
    extern __shared__ char smem[];
    const uint32_t sbase = smem_u32(smem);
    const int tid = threadIdx.x;
    const int lane = tid & 31;
    const int wid  = tid >> 5;
    const int wm = wid >> 2;
    const int wn = wid & 3;
    const int b  = blockIdx.z;
    const int m0 = blockIdx.y * 128;
    const int n0 = blockIdx.x * 128;

    const int p   = tid >> 6;           // 0..3: Ahi, Alo, Bhi, Blo
    const int t64 = tid & 63;
    const u16* gsrc;
    long rowbase;
    int  rstr;
    if (p == 0)      { gsrc = Ahi; rowbase = (long)b * arows + m0; rstr = astr; }
    else if (p == 1) { gsrc = Alo; rowbase = (long)b * arows + m0; rstr = astr; }
    else if (p == 2) { gsrc = Bhi; rowbase = (long)b * brows + n0; rstr = bstr; }
    else             { gsrc = Blo; rowbase = (long)b * brows + n0; rstr = bstr; }
    const uint32_t pdst = sbase + p * PL_SZ;

    auto issue = [&](int t, int s) {
        const int kt = t * 32;
        const uint32_t d0 = pdst + s * STAGE_;
        #pragma unroll
        for (int u = 0; u < 8; u++) {
            int cid = u * 64 + t64;     // 0..511
            int row = cid >> 2;
            int c4  = cid & 3;
            cp16(d0 + row * 80 + c4 * 16,
                 gsrc + (rowbase + row) * (long)rstr + kt + c4 * 8);
        }
        CP_COMMIT();
    };

    float acc[4][4][4];
    #pragma unroll
    for (int mt = 0; mt < 4; mt++)
        #pragma unroll
        for (int nt = 0; nt < 4; nt++)
            #pragma unroll
            for (int e = 0; e < 4; e++) acc[mt][nt][e] = 0.f;

    const int q  = lane & 3;
    const int r4 = lane >> 2;
    auto compute = [&](int s) {
        const char* buf = smem + s * STAGE_;
        #pragma unroll
        for (int h = 0; h < 2; h++) {
            const int kb = (h * 8 + q) * 4;
            uint32_t bh[4][2], bl[4][2];
            #pragma unroll
            for (int nt = 0; nt < 4; nt++) {
                int o = (wn * 32 + nt * 8 + r4) * 80 + kb;
                bh[nt][0] = *(const uint32_t*)(buf + ST_BHI + o);
                bh[nt][1] = *(const uint32_t*)(buf + ST_BHI + o + 16);
                bl[nt][0] = *(const uint32_t*)(buf + ST_BLO + o);
                bl[nt][1] = *(const uint32_t*)(buf + ST_BLO + o + 16);
            }
            #pragma unroll
            for (int mt = 0; mt < 4; mt++) {
                int o1 = (wm * 64 + mt * 16 + r4) * 80 + kb;
                int o2 = o1 + 8 * 80;
                uint32_t ah0 = *(const uint32_t*)(buf + ST_AHI + o1);
                uint32_t ah1 = *(const uint32_t*)(buf + ST_AHI + o2);
                uint32_t ah2 = *(const uint32_t*)(buf + ST_AHI + o1 + 16);
                uint32_t ah3 = *(const uint32_t*)(buf + ST_AHI + o2 + 16);
                uint32_t al0 = *(const uint32_t*)(buf + ST_ALO + o1);
                uint32_t al1 = *(const uint32_t*)(buf + ST_ALO + o2);
                uint32_t al2 = *(const uint32_t*)(buf + ST_ALO + o1 + 16);
                uint32_t al3 = *(const uint32_t*)(buf + ST_ALO + o2 + 16);
                #pragma unroll
                for (int nt = 0; nt < 4; nt++) {
                    mma_bf16(acc[mt][nt], ah0, ah1, ah2, ah3, bh[nt][0], bh[nt][1]);
                    mma_bf16(acc[mt][nt], ah0, ah1, ah2, ah3, bl[nt][0], bl[nt][1]);
                    mma_bf16(acc[mt][nt], al0, al1, al2, al3, bh[nt][0], bh[nt][1]);
                }
            }
        }
    };

    issue(0, 0);
    for (int t = 0; t < kstages; t++) {
        if (t + 1 < kstages) issue(t + 1, (t + 1) & 1);
        else CP_COMMIT();
        CP_WAIT(1);
        __syncthreads();
        compute(t & 1);
        __syncthreads();
    }

    if (mode == 0) {
        #pragma unroll
        for (int mt = 0; mt < 4; mt++) {
            int rA = m0 + wm * 64 + mt * 16 + r4;
            float bv0 = bias[rA];
            float bv8 = bias[rA + 8];
            long r0 = ((long)b * orows + rA) * ostr;
            long r8 = r0 + 8L * ostr;
            #pragma unroll
            for (int nt = 0; nt < 4; nt++) {
                int col = n0 + wn * 32 + nt * 8 + q * 2;
                float2 v0, v1;
                v0.x = acc[mt][nt][0] + bv0;
                v0.y = acc[mt][nt][1] + bv0;
                v1.x = acc[mt][nt][2] + bv8;
                v1.y = acc[mt][nt][3] + bv8;
                *(float2*)&outF[r0 + col] = v0;
                *(float2*)&outF[r8 + col] = v1;
            }
        }
    } else {
        #pragma unroll
        for (int mt = 0; mt < 4; mt++) {
            int rA = m0 + wm * 64 + mt * 16 + r4;
            long r0 = ((long)b * orows + rA) * ostr;
            long r8 = r0 + 8L * ostr;
            #pragma unroll
            for (int nt = 0; nt < 4; nt++) {
                int col = n0 + wn * 32 + nt * 8 + q * 2;
                float bv0 = bias[col];
                float bv1 = bias[col + 1];
                uint32_t h, l;
                split2(acc[mt][nt][0] + bv0, acc[mt][nt][1] + bv1, h, l);
                *(uint32_t*)&oHi[r0 + col] = h;
                *(uint32_t*)&oLo[r0 + col] = l;
                split2(acc[mt][nt][2] + bv0, acc[mt][nt][3] + bv1, h, l);
                *(uint32_t*)&oHi[r8 + col] = h;
                *(uint32_t*)&oLo[r8 + col] = l;
            }
        }
    }
}

// ---------------- energy: Et[j][i] = exp(Qt_i . Kt_j) via MMA ----------------------
// A = Kt rows (QKt cols 64..127), B = Qt rows (cols 0..63). k = 64 single-shot.
// smem plane: 128 rows x 144B (72 bf16) -> conflict-free (word = 36*r4 + q).
#define EPL 18432
#define SMEM_E (4 * EPL)          // 73728

__global__ void __launch_bounds__(256, 2) energy_mma_kernel()
{
    extern __shared__ char smem[];
    __shared__ float sD[128];
    const uint32_t sbase = smem_u32(smem);
    const int tid = threadIdx.x;
    const int lane = tid & 31;
    const int wid  = tid >> 5;
    const int wm = wid >> 2;            // j offset wm*64
    const int wn = wid & 3;             // i offset wn*32
    const int b  = blockIdx.z;
    const int i0 = blockIdx.x * 128;
    const int j0 = blockIdx.y * 128;

    if (tid < 128) sD[tid] = 0.f;

    // load 4 planes via cp.async: p0=Kt_hi p1=Kt_lo p2=Qt_hi p3=Qt_lo
    {
        const int p   = tid >> 6;
        const int t64 = tid & 63;
        const u16* gsrc = (p == 0) ? g_QKthi : (p == 1) ? g_QKtlo
                        : (p == 2) ? g_QKthi : g_QKtlo;
        const int coff = (p < 2) ? 64 : 0;
        const long rowbase = (long)b * N_ + ((p < 2) ? j0 : i0);
        const uint32_t pdst = sbase + p * EPL;
        #pragma unroll
        for (int u = 0; u < 16; u++) {
            int cid = u * 64 + t64;     // 0..1023
            int row = cid >> 3;
            int c8  = (cid & 7) * 8;
            cp16(pdst + row * 144 + c8 * 2,
                 gsrc + (rowbase + row) * 128 + coff + c8);
        }
        CP_COMMIT();
    }
    CP_WAIT(0);
    __syncthreads();

    float acc[4][4][4];
    #pragma unroll
    for (int mt = 0; mt < 4; mt++)
        #pragma unroll
        for (int nt = 0; nt < 4; nt++)
            #pragma unroll
            for (int e = 0; e < 4; e++) acc[mt][nt][e] = 0.f;

    const int q  = lane & 3;
    const int r4 = lane >> 2;
    #pragma unroll
    for (int kc = 0; kc < 4; kc++) {
        const int kb = kc * 32 + q * 4;
        uint32_t bh[4][2], bl[4][2];
        #pragma unroll
        for (int nt = 0; nt < 4; nt++) {
            int o = (wn * 32 + nt * 8 + r4) * 144 + kb;
            bh[nt][0] = *(const uint32_t*)(smem + 2 * EPL + o);
            bh[nt][1] = *(const uint32_t*)(smem + 2 * EPL + o + 16);
            bl[nt][0] = *(const uint32_t*)(smem + 3 * EPL + o);
            bl[nt][1] = *(const uint32_t*)(smem + 3 * EPL + o + 16);
        }
        #pragma unroll
        for (int mt = 0; mt < 4; mt++) {
            int o1 = (wm * 64 + mt * 16 + r4) * 144 + kb;
            int o2 = o1 + 8 * 144;
            uint32_t ah0 = *(const uint32_t*)(smem + o1);
            uint32_t ah1 = *(const uint32_t*)(smem + o2);
            uint32_t ah2 = *(const uint32_t*)(smem + o1 + 16);
            uint32_t ah3 = *(const uint32_t*)(smem + o2 + 16);
            uint32_t al0 = *(const uint32_t*)(smem + EPL + o1);
            uint32_t al1 = *(const uint32_t*)(smem + EPL + o2);
            uint32_t al2 = *(const uint32_t*)(smem + EPL + o1 + 16);
            uint32_t al3 = *(const uint32_t*)(smem + EPL + o2 + 16);
            #pragma unroll
            for (int nt = 0; nt < 4; nt++) {
                mma_bf16(acc[mt][nt], ah0, ah1, ah2, ah3, bh[nt][0], bh[nt][1]);
                mma_bf16(acc[mt][nt], ah0, ah1, ah2, ah3, bl[nt][0], bl[nt][1]);
                mma_bf16(acc[mt][nt], al0, al1, al2, al3, bh[nt][0], bh[nt][1]);
            }
        }
    }

    // epilogue: exp, split-store E planes, accumulate D over j
    float psum[4][2];
    #pragma unroll
    for (int nt = 0; nt < 4; nt++) { psum[nt][0] = 0.f; psum[nt][1] = 0.f; }

    #pragma unroll
    for (int mt = 0; mt < 4; mt++) {
        int jrow = j0 + wm * 64 + mt * 16 + r4;
        long r0 = ((long)b * N_ + jrow) * N_;
        long r8 = r0 + 8L * N_;
        #pragma unroll
        for (int nt = 0; nt < 4; nt++) {
            int col = i0 + wn * 32 + nt * 8 + 2 * q;
            float e0 = __expf(acc[mt][nt][0]);
            float e1 = __expf(acc[mt][nt][1]);
            float e2 = __expf(acc[mt][nt][2]);
            float e3 = __expf(acc[mt][nt][3]);
            uint32_t h, l;
            split2(e0, e1, h, l);
            *(uint32_t*)&g_Ehi[r0 + col] = h;
            *(uint32_t*)&g_Elo[r0 + col] = l;
            split2(e2, e3, h, l);
            *(uint32_t*)&g_Ehi[r8 + col] = h;
            *(uint32_t*)&g_Elo[r8 + col] = l;
            psum[nt][0] += e0 + e2;
            psum[nt][1] += e1 + e3;
        }
    }

    #pragma unroll
    for (int nt = 0; nt < 4; nt++)
        #pragma unroll
        for (int w = 0; w < 2; w++) {
            float v = psum[nt][w];
            v += __shfl_xor_sync(0xffffffffu, v, 4);
            v += __shfl_xor_sync(0xffffffffu, v, 8);
            v += __shfl_xor_sync(0xffffffffu, v, 16);
            if (lane < 4)
                atomicAdd(&sD[wn * 32 + nt * 8 + 2 * lane + w], v);
        }
    __syncthreads();
    if (tid < 128) atomicAdd(&g_D[b * N_ + i0 + tid], sD[tid]);
}

// ---------------- prescale: A planes = split(GV * 1/D) -----------------------------
__global__ __launch_bounds__(256) void prescale_kernel()
{
    long idx4 = (long)blockIdx.x * 256 + threadIdx.x;     // one float4 each
    const long total4 = (long)B_ * C_ * N_ / 4;
    if (idx4 >= total4) return;
    long e0   = idx4 * 4;
    int  i    = (int)(e0 % N_);
    long rest = e0 / N_;
    int  c    = (int)(rest % C_);
    int  b    = (int)(rest / C_);
    float4 y  = *(const float4*)&g_Ygv[((long)b * C_ + c) * N_ + i];
    float4 rr = *(const float4*)&g_D[b * N_ + i];          // 1/D
    y.x *= rr.x; y.y *= rr.y; y.z *= rr.z; y.w *= rr.w;
    uint32_t h01, l01, h23, l23;
    split2(y.x, y.y, h01, l01);
    split2(y.z, y.w, h23, l23);
    *(uint2*)&g_Ahi[e0] = make_uint2(h01, h23);
    *(uint2*)&g_Alo[e0] = make_uint2(l01, l23);
}

// ---------------- launch ----------------------------------------------------------
extern "C" void kernel_launch(void* const* d_in, const int* in_sizes, int n_in,
                              void* d_out, int out_size)
{
    const float* x  = (const float*)d_in[0];
    const float* qw = (const float*)d_in[1];
    const float* qb = (const float*)d_in[2];
    const float* kw = (const float*)d_in[3];
    const float* kb = (const float*)d_in[4];
    const float* vw = (const float*)d_in[5];
    const float* vb = (const float*)d_in[6];
    const float* gw = (const float*)d_in[7];
    const float* gb = (const float*)d_in[8];
    float* out = (float*)d_out;

    void *pxh, *pxl, *pqkh, *pqkl, *pgvh, *pgvl, *pbias,
         *pQh, *pQl, *pYgv, *pEh, *pEl, *pAh, *pAl;
    cudaGetSymbolAddress(&pxh,  g_xthi);
    cudaGetSymbolAddress(&pxl,  g_xtlo);
    cudaGetSymbolAddress(&pqkh, g_Wqkhi);
    cudaGetSymbolAddress(&pqkl, g_Wqklo);
    cudaGetSymbolAddress(&pgvh, g_Wgvhi);
    cudaGetSymbolAddress(&pgvl, g_Wgvlo);
    cudaGetSymbolAddress(&pbias, g_biasA);
    cudaGetSymbolAddress(&pQh,  g_QKthi);
    cudaGetSymbolAddress(&pQl,  g_QKtlo);
    cudaGetSymbolAddress(&pYgv, g_Ygv);
    cudaGetSymbolAddress(&pEh,  g_Ehi);
    cudaGetSymbolAddress(&pEl,  g_Elo);
    cudaGetSymbolAddress(&pAh,  g_Ahi);
    cudaGetSymbolAddress(&pAl,  g_Alo);

    cudaFuncSetAttribute(gemm3_kernel,
                         cudaFuncAttributeMaxDynamicSharedMemorySize, SMEM_G);
    cudaFuncSetAttribute(energy_mma_kernel,
                         cudaFuncAttributeMaxDynamicSharedMemorySize, SMEM_E);

    // K0: weight planes (gamma folded into value)
    build_w_kernel<<<384, 256>>>(qw, qb, kw, kb, vw, vb, gw);

    // x -> transposed bf16 planes
    xsplit_kernel<<<dim3(N_ / 64, C_ / 64, B_), 256>>>(x);

    // QKt[b][i][ck] = xt . Wqk^T + bias  (mode 1: split bf16 out, per-n bias)
    gemm3_kernel<<<dim3(1, N_ / 128, B_), 256, SMEM_G>>>(
        C_ / 32, 1,
        (const u16*)pxh, (const u16*)pxl, N_, C_,
        (const u16*)pqkh, (const u16*)pqkl, 0, C_,
        nullptr, (u16*)pQh, (u16*)pQl, N_, 128, (const float*)pbias);

    // Ygv[b][c][i] = Wgv . xt^T + bias  (mode 0: fp32 out, per-m bias)
    gemm3_kernel<<<dim3(N_ / 128, C_ / 128, B_), 256, SMEM_G>>>(
        C_ / 32, 0,
        (const u16*)pgvh, (const u16*)pgvl, 0, C_,
        (const u16*)pxh, (const u16*)pxl, N_, C_,
        (float*)pYgv, nullptr, nullptr, C_, N_, (const float*)pbias + 128);

    zero_d_kernel<<<(B_ * N_ + 255) / 256, 256>>>();

    // E planes + D sums
    energy_mma_kernel<<<dim3(N_ / 128, N_ / 128, B_), 256, SMEM_E>>>();

    rcp_d_kernel<<<(B_ * N_ + 255) / 256, 256>>>();

    // A planes = split(GV * 1/D)
    {
        long total4 = (long)B_ * C_ * N_ / 4;
        prescale_kernel<<<(int)((total4 + 255) / 256), 256>>>();
    }

    // out[b][c][j] = A . E^T + gb  (mode 0)
    gemm3_kernel<<<dim3(N_ / 128, C_ / 128, B_), 256, SMEM_G>>>(
        N_ / 32, 0,
        (const u16*)pAh, (const u16*)pAl, C_, N_,
        (const u16*)pEh, (const u16*)pEl, N_, N_,
        out, nullptr, nullptr, C_, N_, gb);
}

// round 11
// speedup vs baseline: 2.2818x; 1.1560x over previous
#include <cuda_runtime.h>
#include <cuda_bf16.h>
#include <cuda_fp16.h>
#include <cstdint>

// Problem constants (fixed shapes from reference)
#define B_  8
#define C_  256
#define CK_ 64
#define N_  2304

typedef unsigned short u16;

// ---------------- scratch (__device__ globals) ------------------------------------
__device__ u16   g_xthi[B_ * N_ * C_];        // x transposed [b][n][c], bf16 hi
__device__ u16   g_xtlo[B_ * N_ * C_];        // lo plane
__device__ u16   g_Wqkhi[128 * C_];           // q(64)+k(64) weights [ck][c]
__device__ u16   g_Wqklo[128 * C_];
__device__ u16   g_Wgvhi[C_ * C_];            // (gamma@value) weights [c_out][c]
__device__ u16   g_Wgvlo[C_ * C_];
__device__ float g_biasA[384];                // qb|kb|gv bias
__device__ u16   g_QKthi[B_ * N_ * 128];      // Qt|Kt [b][i][ck] bf16 hi
__device__ u16   g_QKtlo[B_ * N_ * 128];
__device__ float g_Ygv[B_ * C_ * N_];         // GV projection fp32 [b][c][i]
__device__ u16   g_Ef[(long)B_ * N_ * N_];    // exp(QK) [b][j][i], single fp16 plane
__device__ u16   g_Ahi[B_ * C_ * N_];         // (GV/D * 4096) fp16 hi plane [b][c][i]
__device__ u16   g_Alo[B_ * C_ * N_];         // fp16 lo plane
__device__ float g_D[B_ * N_];                // row sums over j, then reciprocals

#define ASCALE 4096.0f

// ---------------- helpers ----------------------------------------------------------
__device__ __forceinline__ void mma_bf16(float* c,
    uint32_t a0, uint32_t a1, uint32_t a2, uint32_t a3, uint32_t b0, uint32_t b1)
{
    asm volatile(
        "mma.sync.aligned.m16n8k16.row.col.f32.bf16.bf16.f32 "
        "{%0,%1,%2,%3}, {%4,%5,%6,%7}, {%8,%9}, {%0,%1,%2,%3};"
        : "+f"(c[0]), "+f"(c[1]), "+f"(c[2]), "+f"(c[3])
        : "r"(a0), "r"(a1), "r"(a2), "r"(a3), "r"(b0), "r"(b1));
}
__device__ __forceinline__ void mma_f16(float* c,
    uint32_t a0, uint32_t a1, uint32_t a2, uint32_t a3, uint32_t b0, uint32_t b1)
{
    asm volatile(
        "mma.sync.aligned.m16n8k16.row.col.f32.f16.f16.f32 "
        "{%0,%1,%2,%3}, {%4,%5,%6,%7}, {%8,%9}, {%0,%1,%2,%3};"
        : "+f"(c[0]), "+f"(c[1]), "+f"(c[2]), "+f"(c[3])
        : "r"(a0), "r"(a1), "r"(a2), "r"(a3), "r"(b0), "r"(b1));
}

// split (a,b) into packed bf16x2 hi + lo planes (low half = a)
__device__ __forceinline__ void split2(float a, float b, uint32_t& hi, uint32_t& lo)
{
    uint32_t h;
    asm("cvt.rn.bf16x2.f32 %0, %1, %2;" : "=r"(h) : "f"(b), "f"(a));
    float ha = __uint_as_float(h << 16);
    float hb = __uint_as_float(h & 0xffff0000u);
    float la = a - ha, lb = b - hb;
    uint32_t l;
    asm("cvt.rn.bf16x2.f32 %0, %1, %2;" : "=r"(l) : "f"(lb), "f"(la));
    hi = h; lo = l;
}

// split (a,b) into packed f16x2 hi + lo planes (low half = a)
__device__ __forceinline__ void split2h(float a, float b, uint32_t& hi, uint32_t& lo)
{
    uint32_t h;
    asm("cvt.rn.f16x2.f32 %0, %1, %2;" : "=r"(h) : "f"(b), "f"(a));
    __half2 hv = *reinterpret_cast<__half2*>(&h);
    float ha = __low2float(hv), hb = __high2float(hv);
    uint32_t l;
    asm("cvt.rn.f16x2.f32 %0, %1, %2;" : "=r"(l) : "f"(b - hb), "f"(a - ha));
    hi = h; lo = l;
}

__device__ __forceinline__ uint32_t smem_u32(const void* p) {
    uint32_t a;
    asm("{ .reg .u64 t; cvta.to.shared.u64 t, %1; cvt.u32.u64 %0, t; }" : "=r"(a) : "l"(p));
    return a;
}
__device__ __forceinline__ void cp16(uint32_t dst, const void* src) {
    asm volatile("cp.async.cg.shared.global [%0], [%1], 16;" :: "r"(dst), "l"(src));
}
#define CP_COMMIT() asm volatile("cp.async.commit_group;" ::: "memory")
#define CP_WAIT(n)  asm volatile("cp.async.wait_group %0;" :: "n"(n) : "memory")

// ---------------- K0: build weights (split planes; gamma folded into value) -------
__global__ __launch_bounds__(256) void build_w_kernel(
    const float* __restrict__ qw, const float* __restrict__ qb,
    const float* __restrict__ kw, const float* __restrict__ kb,
    const float* __restrict__ vw, const float* __restrict__ vb,
    const float* __restrict__ gw)
{
    __shared__ float sg[256];
    __shared__ float srow[256];
    int r = blockIdx.x;
    int t = threadIdx.x;
    if (r < 64) {
        if (t < 128) {
            uint32_t h, l;
            split2(qw[r * C_ + 2 * t], qw[r * C_ + 2 * t + 1], h, l);
            *(uint32_t*)&g_Wqkhi[r * C_ + 2 * t] = h;
            *(uint32_t*)&g_Wqklo[r * C_ + 2 * t] = l;
        }
        if (t == 0) g_biasA[r] = qb[r];
    } else if (r < 128) {
        if (t < 128) {
            uint32_t h, l;
            split2(kw[(r - 64) * C_ + 2 * t], kw[(r - 64) * C_ + 2 * t + 1], h, l);
            *(uint32_t*)&g_Wqkhi[r * C_ + 2 * t] = h;
            *(uint32_t*)&g_Wqklo[r * C_ + 2 * t] = l;
        }
        if (t == 0) g_biasA[r] = kb[r - 64];
    } else {
        int o = r - 128;
        sg[t] = gw[o * C_ + t];
        __syncthreads();
        float acc = 0.f;
        #pragma unroll 8
        for (int c2 = 0; c2 < C_; c2++)
            acc = fmaf(sg[c2], vw[c2 * C_ + t], acc);
        srow[t] = acc;
        if (t == 0) {
            float bb = 0.f;
            for (int c2 = 0; c2 < C_; c2++) bb += sg[c2] * vb[c2];
            g_biasA[r] = bb;
        }
        __syncthreads();
        if (t < 128) {
            uint32_t h, l;
            split2(srow[2 * t], srow[2 * t + 1], h, l);
            *(uint32_t*)&g_Wgvhi[o * C_ + 2 * t] = h;
            *(uint32_t*)&g_Wgvlo[o * C_ + 2 * t] = l;
        }
    }
}

// ---------------- xsplit: x[b][c][n] fp32 -> xt[b][n][c] bf16 hi/lo ----------------
__global__ __launch_bounds__(256) void xsplit_kernel(const float* __restrict__ x)
{
    __shared__ float sm[64][65];
    const int b = blockIdx.z, c0 = blockIdx.y * 64, n0 = blockIdx.x * 64;
    const int tid = threadIdx.x;
    const float* xb = x + ((long)b * C_ + c0) * N_ + n0;
    #pragma unroll
    for (int u = 0; u < 4; u++) {
        int f  = tid + u * 256;
        int c  = f >> 4;
        int n4 = (f & 15) * 4;
        float4 v = *(const float4*)&xb[(long)c * N_ + n4];
        sm[c][n4 + 0] = v.x; sm[c][n4 + 1] = v.y;
        sm[c][n4 + 2] = v.z; sm[c][n4 + 3] = v.w;
    }
    __syncthreads();
    const int nl  = tid & 63;
    const int c16 = (tid >> 6) * 16;
    long obase = ((long)b * N_ + n0 + nl) * C_ + c0 + c16;
    uint32_t hw[8], lw[8];
    #pragma unroll
    for (int m = 0; m < 8; m++)
        split2(sm[c16 + 2 * m][nl], sm[c16 + 2 * m + 1][nl], hw[m], lw[m]);
    *(uint4*)&g_xthi[obase]     = make_uint4(hw[0], hw[1], hw[2], hw[3]);
    *(uint4*)&g_xthi[obase + 8] = make_uint4(hw[4], hw[5], hw[6], hw[7]);
    *(uint4*)&g_xtlo[obase]     = make_uint4(lw[0], lw[1], lw[2], lw[3]);
    *(uint4*)&g_xtlo[obase + 8] = make_uint4(lw[4], lw[5], lw[6], lw[7]);
}

// ---------------- zero / reciprocal D ---------------------------------------------
__global__ void zero_d_kernel() {
    int i = blockIdx.x * 256 + threadIdx.x;
    if (i < B_ * N_) g_D[i] = 0.f;
}
__global__ void rcp_d_kernel() {
    int i = blockIdx.x * 256 + threadIdx.x;
    if (i < B_ * N_) g_D[i] = 1.0f / g_D[i];
}

// ---------------- generalized MMA GEMM (cp.async pipeline) -------------------------
// out[m][n] = sum_k (Ahi+Alo)[m][k] * (Bhi[+Blo])[n][k]
// MODE 0: fp32 out * oscale + per-m bias.  MODE 1: split bf16 out + per-n bias.
// CTA tile MT x NT (warp tile 64x32, MT/64 * NT/32 == 8 warps), k-stage 32.
// smem row stride 80B (16B-aligned for cp.async; conflict-free LDS pattern).
template<int MT, int NT, int DEPTH, bool BLO, bool F16, int MODE>
__global__ void __launch_bounds__(256, 2)
gemm3_kernel(int kstages,
             const u16* __restrict__ Ahi, const u16* __restrict__ Alo,
             int arows, int astr,
             const u16* __restrict__ Bhi, const u16* __restrict__ Blo,
             int brows, int bstr,
             float* __restrict__ outF, u16* __restrict__ oHi, u16* __restrict__ oLo,
             int orows, int ostr, const float* __restrict__ bias, float oscale)
{
    constexpr int NWN   = NT / 32;               // warps along n
    constexpr int PLA   = MT * 80;               // one A plane bytes
    constexpr int BHIO  = 2 * MT * 80;
    constexpr int BLOO  = (2 * MT + NT) * 80;
    constexpr int NB    = BLO ? 2 : 1;
    constexpr int STAGE = (2 * MT + NB * NT) * 80;
    constexpr int CPT   = (2 * MT + NB * NT) * 4 / 256;   // cp16 per thread per stage

    extern __shared__ char smem[];
    const uint32_t sbase = smem_u32(smem);
    const int tid = threadIdx.x;
    const int lane = tid & 31;
    const int wid  = tid >> 5;
    const int wm = wid / NWN;
    const int wn = wid % NWN;
    const int b  = blockIdx.z;
    const int m0 = blockIdx.y * MT;
    const int n0 = blockIdx.x * NT;

    const long ab = (long)b * arows + m0;
    const long bb = (long)b * brows + n0;

    auto issue = [&](int t, int s) {
        const int kt = t * 32;
        const uint32_t d0 = sbase + s * STAGE;
        #pragma unroll
        for (int u = 0; u < CPT; u++) {
            int cid = u * 256 + tid;
            int row = cid >> 2;
            int c4  = cid & 3;
            const u16* src;
            uint32_t doff;
            if (row < MT) {
                src = Ahi + (ab + row) * (long)astr;
                doff = row * 80;
            } else if (row < 2 * MT) {
                src = Alo + (ab + row - MT) * (long)astr;
                doff = PLA + (row - MT) * 80;
            } else if (!BLO || row < 2 * MT + NT) {
                src = Bhi + (bb + row - 2 * MT) * (long)bstr;
                doff = BHIO + (row - 2 * MT) * 80;
            } else {
                src = Blo + (bb + row - 2 * MT - NT) * (long)bstr;
                doff = BLOO + (row - 2 * MT - NT) * 80;
            }
            cp16(d0 + doff + c4 * 16, src + kt + c4 * 8);
        }
        CP_COMMIT();
    };

    float acc[4][4][4];
    #pragma unroll
    for (int mt = 0; mt < 4; mt++)
        #pragma unroll
        for (int nt = 0; nt < 4; nt++)
            #pragma unroll
            for (int e = 0; e < 4; e++) acc[mt][nt][e] = 0.f;

    const int q  = lane & 3;
    const int r4 = lane >> 2;
    auto compute = [&](int s) {
        const char* buf = smem + s * STAGE;
        #pragma unroll
        for (int h = 0; h < 2; h++) {
            const int kb = (h * 8 + q) * 4;
            uint32_t bh[4][2], bl[4][2];
            #pragma unroll
            for (int nt = 0; nt < 4; nt++) {
                int o = (wn * 32 + nt * 8 + r4) * 80 + kb;
                bh[nt][0] = *(const uint32_t*)(buf + BHIO + o);
                bh[nt][1] = *(const uint32_t*)(buf + BHIO + o + 16);
                if (BLO) {
                    bl[nt][0] = *(const uint32_t*)(buf + BLOO + o);
                    bl[nt][1] = *(const uint32_t*)(buf + BLOO + o + 16);
                }
            }
            #pragma unroll
            for (int mt = 0; mt < 4; mt++) {
                int o1 = (wm * 64 + mt * 16 + r4) * 80 + kb;
                int o2 = o1 + 8 * 80;
                uint32_t ah0 = *(const uint32_t*)(buf + o1);
                uint32_t ah1 = *(const uint32_t*)(buf + o2);
                uint32_t ah2 = *(const uint32_t*)(buf + o1 + 16);
                uint32_t ah3 = *(const uint32_t*)(buf + o2 + 16);
                uint32_t al0 = *(const uint32_t*)(buf + PLA + o1);
                uint32_t al1 = *(const uint32_t*)(buf + PLA + o2);
                uint32_t al2 = *(const uint32_t*)(buf + PLA + o1 + 16);
                uint32_t al3 = *(const uint32_t*)(buf + PLA + o2 + 16);
                #pragma unroll
                for (int nt = 0; nt < 4; nt++) {
                    if (F16) {
                        mma_f16(acc[mt][nt], ah0, ah1, ah2, ah3, bh[nt][0], bh[nt][1]);
                        mma_f16(acc[mt][nt], al0, al1, al2, al3, bh[nt][0], bh[nt][1]);
                        if (BLO)
                            mma_f16(acc[mt][nt], ah0, ah1, ah2, ah3, bl[nt][0], bl[nt][1]);
                    } else {
                        mma_bf16(acc[mt][nt], ah0, ah1, ah2, ah3, bh[nt][0], bh[nt][1]);
                        mma_bf16(acc[mt][nt], al0, al1, al2, al3, bh[nt][0], bh[nt][1]);
                        if (BLO)
                            mma_bf16(acc[mt][nt], ah0, ah1, ah2, ah3, bl[nt][0], bl[nt][1]);
                    }
                }
            }
        }
    };

    #pragma unroll
    for (int d = 0; d < DEPTH - 1; d++) issue(d, d);

    for (int t = 0; t < kstages; t++) {
        if (t + DEPTH - 1 < kstages) issue(t + DEPTH - 1, (t + DEPTH - 1) % DEPTH);
        else CP_COMMIT();
        if (DEPTH == 2) { CP_WAIT(1); } else { CP_WAIT(2); }
        __syncthreads();
        compute(t % DEPTH);
        __syncthreads();
    }

    if (MODE == 0) {
        #pragma unroll
        for (int mt = 0; mt < 4; mt++) {
            int rA = m0 + wm * 64 + mt * 16 + r4;
            float bv0 = bias[rA];
            float bv8 = bias[rA + 8];
            long r0 = ((long)b * orows + rA) * ostr;
            long r8 = r0 + 8L * ostr;
            #pragma unroll
            for (int nt = 0; nt < 4; nt++) {
                int col = n0 + wn * 32 + nt * 8 + q * 2;
                float2 v0, v1;
                v0.x = acc[mt][nt][0] * oscale + bv0;
                v0.y = acc[mt][nt][1] * oscale + bv0;
                v1.x = acc[mt][nt][2] * oscale + bv8;
                v1.y = acc[mt][nt][3] * oscale + bv8;
                *(float2*)&outF[r0 + col] = v0;
                *(float2*)&outF[r8 + col] = v1;
            }
        }
    } else {
        #pragma unroll
        for (int mt = 0; mt < 4; mt++) {
            int rA = m0 + wm * 64 + mt * 16 + r4;
            long r0 = ((long)b * orows + rA) * ostr;
            long r8 = r0 + 8L * ostr;
            #pragma unroll
            for (int nt = 0; nt < 4; nt++) {
                int col = n0 + wn * 32 + nt * 8 + q * 2;
                float bv0 = bias[col];
                float bv1 = bias[col + 1];
                uint32_t h, l;
                split2(acc[mt][nt][0] + bv0, acc[mt][nt][1] + bv1, h, l);
                *(uint32_t*)&oHi[r0 + col] = h;
                *(uint32_t*)&oLo[r0 + col] = l;
                split2(acc[mt][nt][2] + bv0, acc[mt][nt][3] + bv1, h, l);
                *(uint32_t*)&oHi[r8 + col] = h;
                *(uint32_t*)&oLo[r8 + col] = l;
            }
        }
    }
}

// ---------------- energy: Ef[j][i] = f16(exp(Qt_i . Kt_j)) via MMA -----------------
// A = Kt rows (QKt cols 64..127), B = Qt rows (cols 0..63). k = 64 single-shot.
#define EPL 18432
#define SMEM_E (4 * EPL)          // 73728

__global__ void __launch_bounds__(256, 2) energy_mma_kernel()
{
    extern __shared__ char smem[];
    __shared__ float sD[128];
    const uint32_t sbase = smem_u32(smem);
    const int tid = threadIdx.x;
    const int lane = tid & 31;
    const int wid  = tid >> 5;
    const int wm = wid >> 2;            // j offset wm*64
    const int wn = wid & 3;             // i offset wn*32
    const int b  = blockIdx.z;
    const int i0 = blockIdx.x * 128;
    const int j0 = blockIdx.y * 128;

    if (tid < 128) sD[tid] = 0.f;

    {
        const int p   = tid >> 6;
        const int t64 = tid & 63;
        const u16* gsrc = (p == 0) ? g_QKthi : (p == 1) ? g_QKtlo
                        : (p == 2) ? g_QKthi : g_QKtlo;
        const int coff = (p < 2) ? 64 : 0;
        const long rowbase = (long)b * N_ + ((p < 2) ? j0 : i0);
        const uint32_t pdst = sbase + p * EPL;
        #pragma unroll
        for (int u = 0; u < 16; u++) {
            int cid = u * 64 + t64;
            int row = cid >> 3;
            int c8  = (cid & 7) * 8;
            cp16(pdst + row * 144 + c8 * 2,
                 gsrc + (rowbase + row) * 128 + coff + c8);
        }
        CP_COMMIT();
    }
    CP_WAIT(0);
    __syncthreads();

    float acc[4][4][4];
    #pragma unroll
    for (int mt = 0; mt < 4; mt++)
        #pragma unroll
        for (int nt = 0; nt < 4; nt++)
            #pragma unroll
            for (int e = 0; e < 4; e++) acc[mt][nt][e] = 0.f;

    const int q  = lane & 3;
    const int r4 = lane >> 2;
    #pragma unroll
    for (int kc = 0; kc < 4; kc++) {
        const int kb = kc * 32 + q * 4;
        uint32_t bh[4][2], bl[4][2];
        #pragma unroll
        for (int nt = 0; nt < 4; nt++) {
            int o = (wn * 32 + nt * 8 + r4) * 144 + kb;
            bh[nt][0] = *(const uint32_t*)(smem + 2 * EPL + o);
            bh[nt][1] = *(const uint32_t*)(smem + 2 * EPL + o + 16);
            bl[nt][0] = *(const uint32_t*)(smem + 3 * EPL + o);
            bl[nt][1] = *(const uint32_t*)(smem + 3 * EPL + o + 16);
        }
        #pragma unroll
        for (int mt = 0; mt < 4; mt++) {
            int o1 = (wm * 64 + mt * 16 + r4) * 144 + kb;
            int o2 = o1 + 8 * 144;
            uint32_t ah0 = *(const uint32_t*)(smem + o1);
            uint32_t ah1 = *(const uint32_t*)(smem + o2);
            uint32_t ah2 = *(const uint32_t*)(smem + o1 + 16);
            uint32_t ah3 = *(const uint32_t*)(smem + o2 + 16);
            uint32_t al0 = *(const uint32_t*)(smem + EPL + o1);
            uint32_t al1 = *(const uint32_t*)(smem + EPL + o2);
            uint32_t al2 = *(const uint32_t*)(smem + EPL + o1 + 16);
            uint32_t al3 = *(const uint32_t*)(smem + EPL + o2 + 16);
            #pragma unroll
            for (int nt = 0; nt < 4; nt++) {
                mma_bf16(acc[mt][nt], ah0, ah1, ah2, ah3, bh[nt][0], bh[nt][1]);
                mma_bf16(acc[mt][nt], ah0, ah1, ah2, ah3, bl[nt][0], bl[nt][1]);
                mma_bf16(acc[mt][nt], al0, al1, al2, al3, bh[nt][0], bh[nt][1]);
            }
        }
    }

    // epilogue: exp, fp16 store, accumulate D over j
    float psum[4][2];
    #pragma unroll
    for (int nt = 0; nt < 4; nt++) { psum[nt][0] = 0.f; psum[nt][1] = 0.f; }

    #pragma unroll
    for (int mt = 0; mt < 4; mt++) {
        int jrow = j0 + wm * 64 + mt * 16 + r4;
        long r0 = ((long)b * N_ + jrow) * N_;
        long r8 = r0 + 8L * N_;
        #pragma unroll
        for (int nt = 0; nt < 4; nt++) {
            int col = i0 + wn * 32 + nt * 8 + 2 * q;
            float e0 = __expf(acc[mt][nt][0]);
            float e1 = __expf(acc[mt][nt][1]);
            float e2 = __expf(acc[mt][nt][2]);
            float e3 = __expf(acc[mt][nt][3]);
            uint32_t p01, p23;
            asm("cvt.rn.f16x2.f32 %0, %1, %2;" : "=r"(p01) : "f"(e1), "f"(e0));
            asm("cvt.rn.f16x2.f32 %0, %1, %2;" : "=r"(p23) : "f"(e3), "f"(e2));
            *(uint32_t*)&g_Ef[r0 + col] = p01;
            *(uint32_t*)&g_Ef[r8 + col] = p23;
            psum[nt][0] += e0 + e2;
            psum[nt][1] += e1 + e3;
        }
    }

    #pragma unroll
    for (int nt = 0; nt < 4; nt++)
        #pragma unroll
        for (int w = 0; w < 2; w++) {
            float v = psum[nt][w];
            v += __shfl_xor_sync(0xffffffffu, v, 4);
            v += __shfl_xor_sync(0xffffffffu, v, 8);
            v += __shfl_xor_sync(0xffffffffu, v, 16);
            if (lane < 4)
                atomicAdd(&sD[wn * 32 + nt * 8 + 2 * lane + w], v);
        }
    __syncthreads();
    if (tid < 128) atomicAdd(&g_D[b * N_ + i0 + tid], sD[tid]);
}

// ---------------- prescale: A planes = f16split(GV * 1/D * ASCALE) -----------------
__global__ __launch_bounds__(256) void prescale_kernel()
{
    long idx4 = (long)blockIdx.x * 256 + threadIdx.x;
    const long total4 = (long)B_ * C_ * N_ / 4;
    if (idx4 >= total4) return;
    long e0   = idx4 * 4;
    int  i    = (int)(e0 % N_);
    long rest = e0 / N_;
    int  c    = (int)(rest % C_);
    int  b    = (int)(rest / C_);
    float4 y  = *(const float4*)&g_Ygv[((long)b * C_ + c) * N_ + i];
    float4 rr = *(const float4*)&g_D[b * N_ + i];          // 1/D
    y.x *= rr.x * ASCALE; y.y *= rr.y * ASCALE;
    y.z *= rr.z * ASCALE; y.w *= rr.w * ASCALE;
    uint32_t h01, l01, h23, l23;
    split2h(y.x, y.y, h01, l01);
    split2h(y.z, y.w, h23, l23);
    *(uint2*)&g_Ahi[e0] = make_uint2(h01, h23);
    *(uint2*)&g_Alo[e0] = make_uint2(l01, l23);
}

// ---------------- launch ----------------------------------------------------------
extern "C" void kernel_launch(void* const* d_in, const int* in_sizes, int n_in,
                              void* d_out, int out_size)
{
    const float* x  = (const float*)d_in[0];
    const float* qw = (const float*)d_in[1];
    const float* qb = (const float*)d_in[2];
    const float* kw = (const float*)d_in[3];
    const float* kb = (const float*)d_in[4];
    const float* vw = (const float*)d_in[5];
    const float* vb = (const float*)d_in[6];
    const float* gw = (const float*)d_in[7];
    const float* gb = (const float*)d_in[8];
    float* out = (float*)d_out;

    void *pxh, *pxl, *pqkh, *pqkl, *pgvh, *pgvl, *pbias,
         *pQh, *pQl, *pYgv, *pEf, *pAh, *pAl;
    cudaGetSymbolAddress(&pxh,  g_xthi);
    cudaGetSymbolAddress(&pxl,  g_xtlo);
    cudaGetSymbolAddress(&pqkh, g_Wqkhi);
    cudaGetSymbolAddress(&pqkl, g_Wqklo);
    cudaGetSymbolAddress(&pgvh, g_Wgvhi);
    cudaGetSymbolAddress(&pgvl, g_Wgvlo);
    cudaGetSymbolAddress(&pbias, g_biasA);
    cudaGetSymbolAddress(&pQh,  g_QKthi);
    cudaGetSymbolAddress(&pQl,  g_QKtlo);
    cudaGetSymbolAddress(&pYgv, g_Ygv);
    cudaGetSymbolAddress(&pEf,  g_Ef);
    cudaGetSymbolAddress(&pAh,  g_Ahi);
    cudaGetSymbolAddress(&pAl,  g_Alo);

    auto kQK  = gemm3_kernel<128, 128, 2, true,  false, 1>;
    auto kGV  = gemm3_kernel<128, 128, 2, true,  false, 0>;
    auto kOUT = gemm3_kernel<256, 64,  2, false, true,  0>;
    const int SMEM_QK  = 2 * (2 * 128 + 2 * 128) * 80;   // 81920
    const int SMEM_OUT = 2 * (2 * 256 + 64) * 80;        // 92160

    cudaFuncSetAttribute(kQK,  cudaFuncAttributeMaxDynamicSharedMemorySize, SMEM_QK);
    cudaFuncSetAttribute(kGV,  cudaFuncAttributeMaxDynamicSharedMemorySize, SMEM_QK);
    cudaFuncSetAttribute(kOUT, cudaFuncAttributeMaxDynamicSharedMemorySize, SMEM_OUT);
    cudaFuncSetAttribute(energy_mma_kernel,
                         cudaFuncAttributeMaxDynamicSharedMemorySize, SMEM_E);

    // K0: weight planes (gamma folded into value)
    build_w_kernel<<<384, 256>>>(qw, qb, kw, kb, vw, vb, gw);

    // x -> transposed bf16 planes
    xsplit_kernel<<<dim3(N_ / 64, C_ / 64, B_), 256>>>(x);

    // QKt[b][i][ck] = xt . Wqk^T + bias  (split bf16 out, per-n bias)
    kQK<<<dim3(1, N_ / 128, B_), 256, SMEM_QK>>>(
        C_ / 32,
        (const u16*)pxh, (const u16*)pxl, N_, C_,
        (const u16*)pqkh, (const u16*)pqkl, 0, C_,
        nullptr, (u16*)pQh, (u16*)pQl, N_, 128, (const float*)pbias, 1.f);

    // Ygv[b][c][i] = Wgv . xt^T + bias  (fp32 out, per-m bias)
    kGV<<<dim3(N_ / 128, C_ / 128, B_), 256, SMEM_QK>>>(
        C_ / 32,
        (const u16*)pgvh, (const u16*)pgvl, 0, C_,
        (const u16*)pxh, (const u16*)pxl, N_, C_,
        (float*)pYgv, nullptr, nullptr, C_, N_, (const float*)pbias + 128, 1.f);

    zero_d_kernel<<<(B_ * N_ + 255) / 256, 256>>>();

    // E plane (fp16) + D sums
    energy_mma_kernel<<<dim3(N_ / 128, N_ / 128, B_), 256, SMEM_E>>>();

    rcp_d_kernel<<<(B_ * N_ + 255) / 256, 256>>>();

    // A planes = f16 split(GV * 1/D * 4096)
    {
        long total4 = (long)B_ * C_ * N_ / 4;
        prescale_kernel<<<(int)((total4 + 255) / 256), 256>>>();
    }

    // out[b][c][j] = (A . Ef^T) / 4096 + gb   (fp16 2-term, MT=256 x NT=64)
    kOUT<<<dim3(N_ / 64, 1, B_), 256, SMEM_OUT>>>(
        N_ / 32,
        (const u16*)pAh, (const u16*)pAl, C_, N_,
        (const u16*)pEf, nullptr, N_, N_,
        out, nullptr, nullptr, C_, N_, gb, 1.f / ASCALE);
}

// round 12
// speedup vs baseline: 2.6603x; 1.1659x over previous
#include <cuda_runtime.h>
#include <cuda_bf16.h>
#include <cuda_fp16.h>
#include <cstdint>

// Problem constants (fixed shapes from reference)
#define B_  8
#define C_  256
#define CK_ 64
#define N_  2304

typedef unsigned short u16;

// ---------------- scratch (__device__ globals) ------------------------------------
__device__ u16   g_xthi[B_ * N_ * C_];        // x transposed [b][n][c], bf16 hi
__device__ u16   g_xtlo[B_ * N_ * C_];        // lo plane
__device__ u16   g_Wqkhi[128 * C_];           // q(64)+k(64) weights [ck][c]
__device__ u16   g_Wqklo[128 * C_];
__device__ u16   g_Wgvhi[C_ * C_];            // (gamma@value) weights [c_out][c]
__device__ u16   g_Wgvlo[C_ * C_];
__device__ float g_biasA[384];                // qb|kb|gv bias
__device__ u16   g_QKthi[B_ * N_ * 128];      // Qt|Kt [b][i][ck] bf16 hi
__device__ u16   g_QKtlo[B_ * N_ * 128];
__device__ u16   g_Ef[(long)B_ * N_ * N_];    // exp(QK) [b][j][i], single fp16 plane
__device__ u16   g_Ahi[B_ * C_ * N_];         // (GV/D * 4096) fp16 hi plane [b][c][i]
__device__ u16   g_Alo[B_ * C_ * N_];         // fp16 lo plane
__device__ float g_D[B_ * N_];                // row sums over j, then reciprocals

#define ASCALE 4096.0f

// ---------------- helpers ----------------------------------------------------------
__device__ __forceinline__ void mma_bf16(float* c,
    uint32_t a0, uint32_t a1, uint32_t a2, uint32_t a3, uint32_t b0, uint32_t b1)
{
    asm volatile(
        "mma.sync.aligned.m16n8k16.row.col.f32.bf16.bf16.f32 "
        "{%0,%1,%2,%3}, {%4,%5,%6,%7}, {%8,%9}, {%0,%1,%2,%3};"
        : "+f"(c[0]), "+f"(c[1]), "+f"(c[2]), "+f"(c[3])
        : "r"(a0), "r"(a1), "r"(a2), "r"(a3), "r"(b0), "r"(b1));
}
__device__ __forceinline__ void mma_f16(float* c,
    uint32_t a0, uint32_t a1, uint32_t a2, uint32_t a3, uint32_t b0, uint32_t b1)
{
    asm volatile(
        "mma.sync.aligned.m16n8k16.row.col.f32.f16.f16.f32 "
        "{%0,%1,%2,%3}, {%4,%5,%6,%7}, {%8,%9}, {%0,%1,%2,%3};"
        : "+f"(c[0]), "+f"(c[1]), "+f"(c[2]), "+f"(c[3])
        : "r"(a0), "r"(a1), "r"(a2), "r"(a3), "r"(b0), "r"(b1));
}
__device__ __forceinline__ void ldsm4(uint32_t* r, uint32_t addr)
{
    asm volatile("ldmatrix.sync.aligned.m8n8.x4.shared.b16 {%0,%1,%2,%3}, [%4];"
        : "=r"(r[0]), "=r"(r[1]), "=r"(r[2]), "=r"(r[3]) : "r"(addr));
}

// split (a,b) into packed bf16x2 hi + lo planes (low half = a)
__device__ __forceinline__ void split2(float a, float b, uint32_t& hi, uint32_t& lo)
{
    uint32_t h;
    asm("cvt.rn.bf16x2.f32 %0, %1, %2;" : "=r"(h) : "f"(b), "f"(a));
    float ha = __uint_as_float(h << 16);
    float hb = __uint_as_float(h & 0xffff0000u);
    float la = a - ha, lb = b - hb;
    uint32_t l;
    asm("cvt.rn.bf16x2.f32 %0, %1, %2;" : "=r"(l) : "f"(lb), "f"(la));
    hi = h; lo = l;
}

// split (a,b) into packed f16x2 hi + lo planes (low half = a)
__device__ __forceinline__ void split2h(float a, float b, uint32_t& hi, uint32_t& lo)
{
    uint32_t h;
    asm("cvt.rn.f16x2.f32 %0, %1, %2;" : "=r"(h) : "f"(b), "f"(a));
    __half2 hv = *reinterpret_cast<__half2*>(&h);
    float ha = __low2float(hv), hb = __high2float(hv);
    uint32_t l;
    asm("cvt.rn.f16x2.f32 %0, %1, %2;" : "=r"(l) : "f"(b - hb), "f"(a - ha));
    hi = h; lo = l;
}

__device__ __forceinline__ uint32_t smem_u32(const void* p) {
    uint32_t a;
    asm("{ .reg .u64 t; cvta.to.shared.u64 t, %1; cvt.u32.u64 %0, t; }" : "=r"(a) : "l"(p));
    return a;
}
__device__ __forceinline__ void cp16(uint32_t dst, const void* src) {
    asm volatile("cp.async.cg.shared.global [%0], [%1], 16;" :: "r"(dst), "l"(src));
}
#define CP_COMMIT() asm volatile("cp.async.commit_group;" ::: "memory")
#define CP_WAIT(n)  asm volatile("cp.async.wait_group %0;" :: "n"(n) : "memory")

// ---------------- K0: build weights (split planes; gamma folded into value) -------
__global__ __launch_bounds__(256) void build_w_kernel(
    const float* __restrict__ qw, const float* __restrict__ qb,
    const float* __restrict__ kw, const float* __restrict__ kb,
    const float* __restrict__ vw, const float* __restrict__ vb,
    const float* __restrict__ gw)
{
    __shared__ float sg[256];
    __shared__ float srow[256];
    int r = blockIdx.x;
    int t = threadIdx.x;
    if (r < 64) {
        if (t < 128) {
            uint32_t h, l;
            split2(qw[r * C_ + 2 * t], qw[r * C_ + 2 * t + 1], h, l);
            *(uint32_t*)&g_Wqkhi[r * C_ + 2 * t] = h;
            *(uint32_t*)&g_Wqklo[r * C_ + 2 * t] = l;
        }
        if (t == 0) g_biasA[r] = qb[r];
    } else if (r < 128) {
        if (t < 128) {
            uint32_t h, l;
            split2(kw[(r - 64) * C_ + 2 * t], kw[(r - 64) * C_ + 2 * t + 1], h, l);
            *(uint32_t*)&g_Wqkhi[r * C_ + 2 * t] = h;
            *(uint32_t*)&g_Wqklo[r * C_ + 2 * t] = l;
        }
        if (t == 0) g_biasA[r] = kb[r - 64];
    } else {
        int o = r - 128;
        sg[t] = gw[o * C_ + t];
        __syncthreads();
        float acc = 0.f;
        #pragma unroll 8
        for (int c2 = 0; c2 < C_; c2++)
            acc = fmaf(sg[c2], vw[c2 * C_ + t], acc);
        srow[t] = acc;
        if (t == 0) {
            float bb = 0.f;
            for (int c2 = 0; c2 < C_; c2++) bb += sg[c2] * vb[c2];
            g_biasA[r] = bb;
        }
        __syncthreads();
        if (t < 128) {
            uint32_t h, l;
            split2(srow[2 * t], srow[2 * t + 1], h, l);
            *(uint32_t*)&g_Wgvhi[o * C_ + 2 * t] = h;
            *(uint32_t*)&g_Wgvlo[o * C_ + 2 * t] = l;
        }
    }
}

// ---------------- xsplit: x[b][c][n] fp32 -> xt[b][n][c] bf16 hi/lo ----------------
__global__ __launch_bounds__(256) void xsplit_kernel(const float* __restrict__ x)
{
    __shared__ float sm[64][65];
    const int b = blockIdx.z, c0 = blockIdx.y * 64, n0 = blockIdx.x * 64;
    const int tid = threadIdx.x;
    const float* xb = x + ((long)b * C_ + c0) * N_ + n0;
    #pragma unroll
    for (int u = 0; u < 4; u++) {
        int f  = tid + u * 256;
        int c  = f >> 4;
        int n4 = (f & 15) * 4;
        float4 v = *(const float4*)&xb[(long)c * N_ + n4];
        sm[c][n4 + 0] = v.x; sm[c][n4 + 1] = v.y;
        sm[c][n4 + 2] = v.z; sm[c][n4 + 3] = v.w;
    }
    __syncthreads();
    const int nl  = tid & 63;
    const int c16 = (tid >> 6) * 16;
    long obase = ((long)b * N_ + n0 + nl) * C_ + c0 + c16;
    uint32_t hw[8], lw[8];
    #pragma unroll
    for (int m = 0; m < 8; m++)
        split2(sm[c16 + 2 * m][nl], sm[c16 + 2 * m + 1][nl], hw[m], lw[m]);
    *(uint4*)&g_xthi[obase]     = make_uint4(hw[0], hw[1], hw[2], hw[3]);
    *(uint4*)&g_xthi[obase + 8] = make_uint4(hw[4], hw[5], hw[6], hw[7]);
    *(uint4*)&g_xtlo[obase]     = make_uint4(lw[0], lw[1], lw[2], lw[3]);
    *(uint4*)&g_xtlo[obase + 8] = make_uint4(lw[4], lw[5], lw[6], lw[7]);
}

// ---------------- zero / reciprocal D ---------------------------------------------
__global__ void zero_d_kernel() {
    int i = blockIdx.x * 256 + threadIdx.x;
    if (i < B_ * N_) g_D[i] = 0.f;
}
__global__ void rcp_d_kernel() {
    int i = blockIdx.x * 256 + threadIdx.x;
    if (i < B_ * N_) g_D[i] = 1.0f / g_D[i];
}

// ---------------- generalized MMA GEMM (128x128 CTA tile, ldmatrix, cp.async) ------
// out[m][n] = sum_k (Ahi+Alo)[m][k] * (Bhi[+Blo])[n][k]
// MODE 0: fp32 out * oscale + per-m bias
// MODE 1: split bf16 out + per-n bias
// MODE 2: split f16 out = (acc + per-m bias) * rcp[n] * ASCALE   (fused prescale)
// k-stage 32, smem row stride 80B. DEPTH=2: two syncs/stage. DEPTH=3: one sync/stage.
template<int DEPTH, bool BLO, bool F16, int MODE>
__global__ void __launch_bounds__(256, 2)
gemm3_kernel(int kstages,
             const u16* __restrict__ Ahi, const u16* __restrict__ Alo,
             int arows, int astr,
             const u16* __restrict__ Bhi, const u16* __restrict__ Blo,
             int brows, int bstr,
             float* __restrict__ outF, u16* __restrict__ oHi, u16* __restrict__ oLo,
             int orows, int ostr, const float* __restrict__ bias,
             const float* __restrict__ rcp, float oscale)
{
    constexpr int PLA   = 128 * 80;              // one A plane bytes
    constexpr int BHIO  = 2 * PLA;
    constexpr int BLOO  = 3 * PLA;
    constexpr int NB    = BLO ? 2 : 1;
    constexpr int STAGE = (2 + NB) * PLA;
    constexpr int CPT   = (2 + NB) * 128 * 4 / 256;   // cp16 per thread per stage

    extern __shared__ char smem[];
    const uint32_t sbase = smem_u32(smem);
    const int tid = threadIdx.x;
    const int lane = tid & 31;
    const int wid  = tid >> 5;
    const int wm = wid >> 2;            // 0..1
    const int wn = wid & 3;             // 0..3
    const int b  = blockIdx.z;
    const int m0 = blockIdx.y * 128;
    const int n0 = blockIdx.x * 128;

    const long ab = (long)b * arows + m0;
    const long bb = (long)b * brows + n0;

    auto issue = [&](int t, int s) {
        const int kt = t * 32;
        const uint32_t d0 = sbase + s * STAGE;
        #pragma unroll
        for (int u = 0; u < CPT; u++) {
            int cid = u * 256 + tid;
            int row = cid >> 2;
            int c4  = cid & 3;
            const u16* src;
            uint32_t doff;
            if (row < 128) {
                src = Ahi + (ab + row) * (long)astr;
                doff = row * 80;
            } else if (row < 256) {
                src = Alo + (ab + row - 128) * (long)astr;
                doff = PLA + (row - 128) * 80;
            } else if (!BLO || row < 384) {
                src = Bhi + (bb + row - 256) * (long)bstr;
                doff = BHIO + (row - 256) * 80;
            } else {
                src = Blo + (bb + row - 384) * (long)bstr;
                doff = BLOO + (row - 384) * 80;
            }
            cp16(d0 + doff + c4 * 16, src + kt + c4 * 8);
        }
        CP_COMMIT();
    };

    float acc[4][4][4];
    #pragma unroll
    for (int mt = 0; mt < 4; mt++)
        #pragma unroll
        for (int nt = 0; nt < 4; nt++)
            #pragma unroll
            for (int e = 0; e < 4; e++) acc[mt][nt][e] = 0.f;

    const int q  = lane & 3;
    const int r4 = lane >> 2;
    const int g  = lane >> 3;
    const int l7 = lane & 7;
    // ldmatrix lane-address offsets (row stride 80B, conflict-free)
    const uint32_t aoff  = (wm * 64 + l7 + ((g & 1) << 3)) * 80 + ((g >> 1) << 4);
    const uint32_t boff0 = (wn * 32 + ((g >> 1)) * 8 + l7) * 80 + ((g & 1) << 4);
    const uint32_t boff1 = boff0 + 16 * 80;

    auto compute = [&](int s) {
        const uint32_t buf = sbase + s * STAGE;
        #pragma unroll
        for (int h = 0; h < 2; h++) {
            const uint32_t kb = h * 32;
            uint32_t bh[4][2], bl[4][2], r[4];
            ldsm4(r, buf + BHIO + boff0 + kb);
            bh[0][0] = r[0]; bh[0][1] = r[1]; bh[1][0] = r[2]; bh[1][1] = r[3];
            ldsm4(r, buf + BHIO + boff1 + kb);
            bh[2][0] = r[0]; bh[2][1] = r[1]; bh[3][0] = r[2]; bh[3][1] = r[3];
            if (BLO) {
                ldsm4(r, buf + BLOO + boff0 + kb);
                bl[0][0] = r[0]; bl[0][1] = r[1]; bl[1][0] = r[2]; bl[1][1] = r[3];
                ldsm4(r, buf + BLOO + boff1 + kb);
                bl[2][0] = r[0]; bl[2][1] = r[1]; bl[3][0] = r[2]; bl[3][1] = r[3];
            }
            #pragma unroll
            for (int mt = 0; mt < 4; mt++) {
                uint32_t ah[4], al[4];
                ldsm4(ah, buf + aoff + mt * 1280 + kb);
                ldsm4(al, buf + PLA + aoff + mt * 1280 + kb);
                #pragma unroll
                for (int nt = 0; nt < 4; nt++) {
                    if (F16) {
                        mma_f16(acc[mt][nt], ah[0], ah[1], ah[2], ah[3], bh[nt][0], bh[nt][1]);
                        mma_f16(acc[mt][nt], al[0], al[1], al[2], al[3], bh[nt][0], bh[nt][1]);
                        if (BLO)
                            mma_f16(acc[mt][nt], ah[0], ah[1], ah[2], ah[3], bl[nt][0], bl[nt][1]);
                    } else {
                        mma_bf16(acc[mt][nt], ah[0], ah[1], ah[2], ah[3], bh[nt][0], bh[nt][1]);
                        mma_bf16(acc[mt][nt], al[0], al[1], al[2], al[3], bh[nt][0], bh[nt][1]);
                        if (BLO)
                            mma_bf16(acc[mt][nt], ah[0], ah[1], ah[2], ah[3], bl[nt][0], bl[nt][1]);
                    }
                }
            }
        }
    };

    if (DEPTH == 3) {
        issue(0, 0); issue(1, 1);
        for (int t = 0; t < kstages; t++) {
            CP_WAIT(1);
            __syncthreads();
            if (t + 2 < kstages) issue(t + 2, (t + 2) % 3);
            else CP_COMMIT();
            compute(t % 3);
        }
    } else {
        issue(0, 0);
        for (int t = 0; t < kstages; t++) {
            if (t + 1 < kstages) issue(t + 1, (t + 1) & 1);
            else CP_COMMIT();
            CP_WAIT(1);
            __syncthreads();
            compute(t & 1);
            __syncthreads();
        }
    }

    if (MODE == 0) {
        #pragma unroll
        for (int mt = 0; mt < 4; mt++) {
            int rA = m0 + wm * 64 + mt * 16 + r4;
            float bv0 = bias[rA];
            float bv8 = bias[rA + 8];
            long r0 = ((long)b * orows + rA) * ostr;
            long r8 = r0 + 8L * ostr;
            #pragma unroll
            for (int nt = 0; nt < 4; nt++) {
                int col = n0 + wn * 32 + nt * 8 + q * 2;
                float2 v0, v1;
                v0.x = acc[mt][nt][0] * oscale + bv0;
                v0.y = acc[mt][nt][1] * oscale + bv0;
                v1.x = acc[mt][nt][2] * oscale + bv8;
                v1.y = acc[mt][nt][3] * oscale + bv8;
                *(float2*)&outF[r0 + col] = v0;
                *(float2*)&outF[r8 + col] = v1;
            }
        }
    } else if (MODE == 1) {
        #pragma unroll
        for (int mt = 0; mt < 4; mt++) {
            int rA = m0 + wm * 64 + mt * 16 + r4;
            long r0 = ((long)b * orows + rA) * ostr;
            long r8 = r0 + 8L * ostr;
            #pragma unroll
            for (int nt = 0; nt < 4; nt++) {
                int col = n0 + wn * 32 + nt * 8 + q * 2;
                float bv0 = bias[col];
                float bv1 = bias[col + 1];
                uint32_t h, l;
                split2(acc[mt][nt][0] + bv0, acc[mt][nt][1] + bv1, h, l);
                *(uint32_t*)&oHi[r0 + col] = h;
                *(uint32_t*)&oLo[r0 + col] = l;
                split2(acc[mt][nt][2] + bv0, acc[mt][nt][3] + bv1, h, l);
                *(uint32_t*)&oHi[r8 + col] = h;
                *(uint32_t*)&oLo[r8 + col] = l;
            }
        }
    } else {
        #pragma unroll
        for (int mt = 0; mt < 4; mt++) {
            int rA = m0 + wm * 64 + mt * 16 + r4;
            float bv0 = bias[rA];
            float bv8 = bias[rA + 8];
            long r0 = ((long)b * orows + rA) * ostr;
            long r8 = r0 + 8L * ostr;
            #pragma unroll
            for (int nt = 0; nt < 4; nt++) {
                int col = n0 + wn * 32 + nt * 8 + q * 2;
                float rc0 = rcp[(long)b * N_ + col] * ASCALE;
                float rc1 = rcp[(long)b * N_ + col + 1] * ASCALE;
                uint32_t h, l;
                split2h((acc[mt][nt][0] + bv0) * rc0, (acc[mt][nt][1] + bv0) * rc1, h, l);
                *(uint32_t*)&oHi[r0 + col] = h;
                *(uint32_t*)&oLo[r0 + col] = l;
                split2h((acc[mt][nt][2] + bv8) * rc0, (acc[mt][nt][3] + bv8) * rc1, h, l);
                *(uint32_t*)&oHi[r8 + col] = h;
                *(uint32_t*)&oLo[r8 + col] = l;
            }
        }
    }
}

// ---------------- energy: Ef[j][i] = f16(exp(Qt_i . Kt_j)) via MMA -----------------
// A = Kt rows (QKt cols 64..127), B = Qt rows (cols 0..63). k = 64 single-shot.
#define EPL 18432
#define SMEM_E (4 * EPL)          // 73728

__global__ void __launch_bounds__(256, 2) energy_mma_kernel()
{
    extern __shared__ char smem[];
    __shared__ float sD[128];
    const uint32_t sbase = smem_u32(smem);
    const int tid = threadIdx.x;
    const int lane = tid & 31;
    const int wid  = tid >> 5;
    const int wm = wid >> 2;            // j offset wm*64
    const int wn = wid & 3;             // i offset wn*32
    const int b  = blockIdx.z;
    const int i0 = blockIdx.x * 128;
    const int j0 = blockIdx.y * 128;

    if (tid < 128) sD[tid] = 0.f;

    {
        const int p   = tid >> 6;
        const int t64 = tid & 63;
        const u16* gsrc = (p == 0) ? g_QKthi : (p == 1) ? g_QKtlo
                        : (p == 2) ? g_QKthi : g_QKtlo;
        const int coff = (p < 2) ? 64 : 0;
        const long rowbase = (long)b * N_ + ((p < 2) ? j0 : i0);
        const uint32_t pdst = sbase + p * EPL;
        #pragma unroll
        for (int u = 0; u < 16; u++) {
            int cid = u * 64 + t64;
            int row = cid >> 3;
            int c8  = (cid & 7) * 8;
            cp16(pdst + row * 144 + c8 * 2,
                 gsrc + (rowbase + row) * 128 + coff + c8);
        }
        CP_COMMIT();
    }
    CP_WAIT(0);
    __syncthreads();

    float acc[4][4][4];
    #pragma unroll
    for (int mt = 0; mt < 4; mt++)
        #pragma unroll
        for (int nt = 0; nt < 4; nt++)
            #pragma unroll
            for (int e = 0; e < 4; e++) acc[mt][nt][e] = 0.f;

    const int q  = lane & 3;
    const int r4 = lane >> 2;
    const int g  = lane >> 3;
    const int l7 = lane & 7;
    const uint32_t aoff  = (wm * 64 + l7 + ((g & 1) << 3)) * 144 + ((g >> 1) << 4);
    const uint32_t boff0 = (wn * 32 + ((g >> 1)) * 8 + l7) * 144 + ((g & 1) << 4);
    const uint32_t boff1 = boff0 + 16 * 144;

    #pragma unroll
    for (int kc = 0; kc < 4; kc++) {
        const uint32_t kb = kc * 32;
        uint32_t bh[4][2], bl[4][2], r[4];
        ldsm4(r, sbase + 2 * EPL + boff0 + kb);
        bh[0][0] = r[0]; bh[0][1] = r[1]; bh[1][0] = r[2]; bh[1][1] = r[3];
        ldsm4(r, sbase + 2 * EPL + boff1 + kb);
        bh[2][0] = r[0]; bh[2][1] = r[1]; bh[3][0] = r[2]; bh[3][1] = r[3];
        ldsm4(r, sbase + 3 * EPL + boff0 + kb);
        bl[0][0] = r[0]; bl[0][1] = r[1]; bl[1][0] = r[2]; bl[1][1] = r[3];
        ldsm4(r, sbase + 3 * EPL + boff1 + kb);
        bl[2][0] = r[0]; bl[2][1] = r[1]; bl[3][0] = r[2]; bl[3][1] = r[3];
        #pragma unroll
        for (int mt = 0; mt < 4; mt++) {
            uint32_t ah[4], al[4];
            ldsm4(ah, sbase + aoff + mt * 2304 + kb);
            ldsm4(al, sbase + EPL + aoff + mt * 2304 + kb);
            #pragma unroll
            for (int nt = 0; nt < 4; nt++) {
                mma_bf16(acc[mt][nt], ah[0], ah[1], ah[2], ah[3], bh[nt][0], bh[nt][1]);
                mma_bf16(acc[mt][nt], ah[0], ah[1], ah[2], ah[3], bl[nt][0], bl[nt][1]);
                mma_bf16(acc[mt][nt], al[0], al[1], al[2], al[3], bh[nt][0], bh[nt][1]);
            }
        }
    }

    // epilogue: exp, fp16 store, accumulate D over j
    float psum[4][2];
    #pragma unroll
    for (int nt = 0; nt < 4; nt++) { psum[nt][0] = 0.f; psum[nt][1] = 0.f; }

    #pragma unroll
    for (int mt = 0; mt < 4; mt++) {
        int jrow = j0 + wm * 64 + mt * 16 + r4;
        long r0 = ((long)b * N_ + jrow) * N_;
        long r8 = r0 + 8L * N_;
        #pragma unroll
        for (int nt = 0; nt < 4; nt++) {
            int col = i0 + wn * 32 + nt * 8 + 2 * q;
            float e0 = __expf(acc[mt][nt][0]);
            float e1 = __expf(acc[mt][nt][1]);
            float e2 = __expf(acc[mt][nt][2]);
            float e3 = __expf(acc[mt][nt][3]);
            uint32_t p01, p23;
            asm("cvt.rn.f16x2.f32 %0, %1, %2;" : "=r"(p01) : "f"(e1), "f"(e0));
            asm("cvt.rn.f16x2.f32 %0, %1, %2;" : "=r"(p23) : "f"(e3), "f"(e2));
            *(uint32_t*)&g_Ef[r0 + col] = p01;
            *(uint32_t*)&g_Ef[r8 + col] = p23;
            psum[nt][0] += e0 + e2;
            psum[nt][1] += e1 + e3;
        }
    }

    #pragma unroll
    for (int nt = 0; nt < 4; nt++)
        #pragma unroll
        for (int w = 0; w < 2; w++) {
            float v = psum[nt][w];
            v += __shfl_xor_sync(0xffffffffu, v, 4);
            v += __shfl_xor_sync(0xffffffffu, v, 8);
            v += __shfl_xor_sync(0xffffffffu, v, 16);
            if (lane < 4)
                atomicAdd(&sD[wn * 32 + nt * 8 + 2 * lane + w], v);
        }
    __syncthreads();
    if (tid < 128) atomicAdd(&g_D[b * N_ + i0 + tid], sD[tid]);
}

// ---------------- launch ----------------------------------------------------------
extern "C" void kernel_launch(void* const* d_in, const int* in_sizes, int n_in,
                              void* d_out, int out_size)
{
    const float* x  = (const float*)d_in[0];
    const float* qw = (const float*)d_in[1];
    const float* qb = (const float*)d_in[2];
    const float* kw = (const float*)d_in[3];
    const float* kb = (const float*)d_in[4];
    const float* vw = (const float*)d_in[5];
    const float* vb = (const float*)d_in[6];
    const float* gw = (const float*)d_in[7];
    const float* gb = (const float*)d_in[8];
    float* out = (float*)d_out;

    void *pxh, *pxl, *pqkh, *pqkl, *pgvh, *pgvl, *pbias,
         *pQh, *pQl, *pEf, *pAh, *pAl, *pD;
    cudaGetSymbolAddress(&pxh,  g_xthi);
    cudaGetSymbolAddress(&pxl,  g_xtlo);
    cudaGetSymbolAddress(&pqkh, g_Wqkhi);
    cudaGetSymbolAddress(&pqkl, g_Wqklo);
    cudaGetSymbolAddress(&pgvh, g_Wgvhi);
    cudaGetSymbolAddress(&pgvl, g_Wgvlo);
    cudaGetSymbolAddress(&pbias, g_biasA);
    cudaGetSymbolAddress(&pQh,  g_QKthi);
    cudaGetSymbolAddress(&pQl,  g_QKtlo);
    cudaGetSymbolAddress(&pEf,  g_Ef);
    cudaGetSymbolAddress(&pAh,  g_Ahi);
    cudaGetSymbolAddress(&pAl,  g_Alo);
    cudaGetSymbolAddress(&pD,   g_D);

    auto kQK  = gemm3_kernel<2, true,  false, 1>;
    auto kGV  = gemm3_kernel<2, true,  false, 2>;
    auto kOUT = gemm3_kernel<3, false, true,  0>;
    const int SMEM_QK  = 2 * 4 * 128 * 80;   // 81920
    const int SMEM_OUT = 3 * 3 * 128 * 80;   // 92160

    cudaFuncSetAttribute(kQK,  cudaFuncAttributeMaxDynamicSharedMemorySize, SMEM_QK);
    cudaFuncSetAttribute(kGV,  cudaFuncAttributeMaxDynamicSharedMemorySize, SMEM_QK);
    cudaFuncSetAttribute(kOUT, cudaFuncAttributeMaxDynamicSharedMemorySize, SMEM_OUT);
    cudaFuncSetAttribute(energy_mma_kernel,
                         cudaFuncAttributeMaxDynamicSharedMemorySize, SMEM_E);

    // K0: weight planes (gamma folded into value)
    build_w_kernel<<<384, 256>>>(qw, qb, kw, kb, vw, vb, gw);

    // x -> transposed bf16 planes
    xsplit_kernel<<<dim3(N_ / 64, C_ / 64, B_), 256>>>(x);

    // QKt[b][i][ck] = xt . Wqk^T + bias  (split bf16 out, per-n bias)
    kQK<<<dim3(1, N_ / 128, B_), 256, SMEM_QK>>>(
        C_ / 32,
        (const u16*)pxh, (const u16*)pxl, N_, C_,
        (const u16*)pqkh, (const u16*)pqkl, 0, C_,
        nullptr, (u16*)pQh, (u16*)pQl, N_, 128, (const float*)pbias,
        nullptr, 1.f);

    zero_d_kernel<<<(B_ * N_ + 255) / 256, 256>>>();

    // E plane (fp16) + D sums
    energy_mma_kernel<<<dim3(N_ / 128, N_ / 128, B_), 256, SMEM_E>>>();

    rcp_d_kernel<<<(B_ * N_ + 255) / 256, 256>>>();

    // A planes = f16 split((Wgv . xt^T + bias) * 1/D * 4096)  (fused prescale)
    kGV<<<dim3(N_ / 128, C_ / 128, B_), 256, SMEM_QK>>>(
        C_ / 32,
        (const u16*)pgvh, (const u16*)pgvl, 0, C_,
        (const u16*)pxh, (const u16*)pxl, N_, C_,
        nullptr, (u16*)pAh, (u16*)pAl, C_, N_, (const float*)pbias + 128,
        (const float*)pD, 1.f);

    // out[b][c][j] = (A . Ef^T) / 4096 + gb   (fp16 2-term, depth-3 single-sync)
    kOUT<<<dim3(N_ / 128, C_ / 128, B_), 256, SMEM_OUT>>>(
        N_ / 32,
        (const u16*)pAh, (const u16*)pAl, C_, N_,
        (const u16*)pEf, nullptr, N_, N_,
        out, nullptr, nullptr, C_, N_, gb,
        nullptr, 1.f / ASCALE);
}